// round 14
// baseline (speedup 1.0000x reference)
#include <cuda_runtime.h>
#include <cuda_fp16.h>
#include <math.h>
#include <stdint.h>

#define BB     4
#define NSEQ   8192
#define DM     512
#define MTOT   (BB * NSEQ)       // 32768
#define SPLITK 16
#define KC     (NSEQ / SPLITK)   // 512
#define NCHK   (NSEQ / 64)       // 128 mean partial chunks

// ---------------- scratch (static device memory; referenced ONLY from device
// code — host-side use of these symbols silently hits host memory via ATS) ---
__device__ float g_P [SPLITK * BB * DM * DM];   // X^T X split-K partials
__device__ float g_Pm[BB * NCHK * DM];          // column-sum partials (fused)
__device__ float g_xm[BB * DM];                 // mean over n of X
__device__ float g_first[BB * DM];
__device__ __half g_Xh [(size_t)MTOT * DM];     // fp16 X       [b*n][d]
__device__ __half g_Xt [(size_t)BB * DM * NSEQ];// fp16 X^T     [b][d][n]
__device__ __half g_Gh [BB * DM * DM];          // fp16 G = X^T X (symmetric)
__device__ __half g_M1h[BB * DM * DM];          // fp16 Wv @ G
__device__ __half g_KVh[BB * DM * DM];          // fp16 KV^T    [j][k]
__device__ __half g_Wvh[DM * DM];               // fp16 Wv
__device__ __half g_Wth[DM * DM];               // fp16 Wtheta

// 20 (128-row tile, 64-col half) units covering the upper triangle
__constant__ int c_ti20[20] = {0,0,0,0,0,0,0,0, 1,1,1,1,1,1, 2,2,2,2, 3,3};
__constant__ int c_tj20[20] = {0,0,1,1,2,2,3,3, 1,1,2,2,3,3, 2,2,3,3, 3,3};
__constant__ int c_jh20[20] = {0,1,0,1,0,1,0,1, 0,1,0,1,0,1, 0,1,0,1, 0,1};

#define SW128(x) ((x) ^ (((x) >> 3) & 0x70))

__device__ __forceinline__ uint32_t smem_to_u32(const void* p) {
    uint32_t a;
    asm("{ .reg .u64 t; cvta.to.shared.u64 t, %1; cvt.u32.u64 %0, t; }"
        : "=r"(a) : "l"(p));
    return a;
}
__device__ __forceinline__ void ldmx4(uint32_t r[4], uint32_t addr) {
    asm volatile("ldmatrix.sync.aligned.m8n8.x4.shared.b16 {%0,%1,%2,%3}, [%4];"
        : "=r"(r[0]), "=r"(r[1]), "=r"(r[2]), "=r"(r[3]) : "r"(addr));
}
__device__ __forceinline__ void mma16816(float c[4], const uint32_t a[4],
                                         const uint32_t b[2]) {
    asm volatile("mma.sync.aligned.m16n8k16.row.col.f32.f16.f16.f32 "
        "{%0,%1,%2,%3}, {%4,%5,%6,%7}, {%8,%9}, {%0,%1,%2,%3};"
        : "+f"(c[0]), "+f"(c[1]), "+f"(c[2]), "+f"(c[3])
        : "r"(a[0]), "r"(a[1]), "r"(a[2]), "r"(a[3]), "r"(b[0]), "r"(b[1]));
}
__device__ __forceinline__ void cp_async16(uint32_t dst, const void* src) {
    asm volatile("cp.async.cg.shared.global [%0], [%1], 16;"
        :: "r"(dst), "l"(src) : "memory");
}
#define CP_COMMIT() asm volatile("cp.async.commit_group;" ::: "memory")
#define CP_WAIT(n)  asm volatile("cp.async.wait_group %0;" :: "n"(n) : "memory")

// ---- 128(M)x64(N) tile smem layout: A 2x16KB @0, B 2x8KB @32768 ----
#define SM_A   0
#define SM_B   32768
#define MMA_SMEM 49152

// stage: A = 128 rows x 64 halfs, B = 64 rows x 64 halfs (1536 f16x8 slots)
#define NT_STAGE64(Abase, Bbase, stride, kc, buf) do { \
        _Pragma("unroll") \
        for (int i = tid; i < 1536; i += 256) { \
            const int arr = (i >= 1024); \
            const int idx = arr ? (i - 1024) : i; \
            const int row = idx >> 3; \
            const int cg  = idx & 7; \
            const uint32_t sw = SW128((uint32_t)(row * 128 + cg * 16)); \
            const uint32_t dst = sb + (arr ? (SM_B + (buf) * 8192) \
                                           : (SM_A + (buf) * 16384)) + sw; \
            const __half* src = (arr ? (Bbase) : (Abase)) \
                + (size_t)row * (stride) + (kc) * 64 + cg * 8; \
            cp_async16(dst, src); \
        } \
        CP_COMMIT(); \
    } while (0)

// ============================================================================
// fp16 conversion of X + fused transpose + fused column-sum partials.
// grid (NSEQ/64, DM/64, BB), 256 threads.
// ============================================================================
__global__ void convert_x_kernel(const float* __restrict__ X)
{
    __shared__ __half s[64][72];
    __shared__ float  psum[16][64];
    const int b  = blockIdx.z;
    const int n0 = blockIdx.x * 64;
    const int d0 = blockIdx.y * 64;
    const int t  = threadIdx.x;

    float4 cs = make_float4(0.f, 0.f, 0.f, 0.f);
#pragma unroll
    for (int i = t; i < 1024; i += 256) {
        const int row = i >> 4;
        const int cq  = (i & 15) << 2;
        float4 v = *(const float4*)(X + ((size_t)b * NSEQ + n0 + row) * DM + d0 + cq);
        cs.x += v.x; cs.y += v.y; cs.z += v.z; cs.w += v.w;
        __half h0 = __float2half_rn(v.x), h1 = __float2half_rn(v.y);
        __half h2 = __float2half_rn(v.z), h3 = __float2half_rn(v.w);
        uint2 u; __half* ph = (__half*)&u;
        ph[0] = h0; ph[1] = h1; ph[2] = h2; ph[3] = h3;
        *(uint2*)(g_Xh + ((size_t)b * NSEQ + n0 + row) * DM + d0 + cq) = u;
        s[cq + 0][row] = h0; s[cq + 1][row] = h1;
        s[cq + 2][row] = h2; s[cq + 3][row] = h3;
    }
    *(float4*)&psum[t >> 4][(t & 15) << 2] = cs;
    __syncthreads();

#pragma unroll
    for (int i = t; i < 1024; i += 256) {
        const int dr = i >> 4;
        const int nq = (i & 15) << 2;
        uint2 u; __half* ph = (__half*)&u;
        ph[0] = s[dr][nq]; ph[1] = s[dr][nq + 1];
        ph[2] = s[dr][nq + 2]; ph[3] = s[dr][nq + 3];
        *(uint2*)(g_Xt + ((size_t)b * DM + d0 + dr) * NSEQ + n0 + nq) = u;
    }

    if (t < 64) {
        float v = 0.f;
#pragma unroll
        for (int rg = 0; rg < 16; rg++) v += psum[rg][t];
        g_Pm[((size_t)b * NCHK + blockIdx.x) * DM + d0 + t] = v;
    }
}

// fp16 conversion of Wv / Wtheta. grid 256, 256 thr.
__global__ void convert_w_kernel(const float* __restrict__ Wv,
                                 const float* __restrict__ Wt)
{
    const int blk = blockIdx.x;
    const float* src = (blk < 128) ? Wv : Wt;
    __half* dst = (blk < 128) ? g_Wvh : g_Wth;
    const size_t base = ((size_t)(blk & 127) * 256 + threadIdx.x) * 8;
    float4 v0 = *(const float4*)(src + base);
    float4 v1 = *(const float4*)(src + base + 4);
    uint4 u; __half* ph = (__half*)&u;
    ph[0] = __float2half_rn(v0.x); ph[1] = __float2half_rn(v0.y);
    ph[2] = __float2half_rn(v0.z); ph[3] = __float2half_rn(v0.w);
    ph[4] = __float2half_rn(v1.x); ph[5] = __float2half_rn(v1.y);
    ph[6] = __float2half_rn(v1.z); ph[7] = __float2half_rn(v1.w);
    *(uint4*)(dst + base) = u;
}

// ============================================================================
// X^T X on fp16 HMMA, 128x64 units: P[s][b][128 i-rows][64 j-cols].
// grid (20, BB*SPLITK) = 1280 CTAs, 256 threads, K=512 (8 chunks of 64).
// ============================================================================
__global__ void __launch_bounds__(256, 2) xtx_mma_kernel()
{
    extern __shared__ char smem[];
    const uint32_t sb = smem_to_u32(smem);
    const int tid  = threadIdx.x;
    const int wid  = tid >> 5;
    const int lane = tid & 31;
    const int wm   = wid >> 2;          // 0..1 (M 64-halves)
    const int wn   = wid & 3;           // 0..3 (N 16-quarters)
    const int ti   = c_ti20[blockIdx.x];
    const int tj   = c_tj20[blockIdx.x];
    const int jh   = c_jh20[blockIdx.x];
    const int b    = blockIdx.y / SPLITK;
    const int s    = blockIdx.y % SPLITK;
    const __half* __restrict__ Abase =
        g_Xt + ((size_t)b * DM + ti * 128) * NSEQ + (size_t)s * KC;
    const __half* __restrict__ Bbase =
        g_Xt + ((size_t)b * DM + tj * 128 + jh * 64) * NSEQ + (size_t)s * KC;

    const int a_row = wm * 64 + ((lane >> 3) & 1) * 8 + (lane & 7);
    const int a_byt = ((lane >> 4) & 1) * 16;
    const int b_row = wn * 16 + ((lane >> 4) & 1) * 8 + (lane & 7);
    const int b_byt = ((lane >> 3) & 1) * 16;

    float acc[4][2][4];
#pragma unroll
    for (int mt = 0; mt < 4; mt++)
#pragma unroll
        for (int nt = 0; nt < 2; nt++)
#pragma unroll
            for (int q = 0; q < 4; q++) acc[mt][nt][q] = 0.f;

    NT_STAGE64(Abase, Bbase, NSEQ, 0, 0);

    const int NCH = KC / 64;     // 8
    for (int kc = 0; kc < NCH; kc++) {
        const int cur = kc & 1;
        if (kc + 1 < NCH) {
            NT_STAGE64(Abase, Bbase, NSEQ, kc + 1, cur ^ 1);
            CP_WAIT(1);
        } else {
            CP_WAIT(0);
        }
        __syncthreads();

        const uint32_t abase = sb + SM_A + cur * 16384;
        const uint32_t bbase = sb + SM_B + cur * 8192;
#pragma unroll
        for (int kk = 0; kk < 4; kk++) {
            uint32_t a[4][4], bb[2][2];
#pragma unroll
            for (int mt = 0; mt < 4; mt++) {
                uint32_t off = (uint32_t)((a_row + mt * 16) * 128 + kk * 32 + a_byt);
                ldmx4(a[mt], abase + SW128(off));
            }
            {
                uint32_t off = (uint32_t)(b_row * 128 + kk * 32 + b_byt);
                uint32_t r[4];
                ldmx4(r, bbase + SW128(off));
                bb[0][0] = r[0]; bb[0][1] = r[1];
                bb[1][0] = r[2]; bb[1][1] = r[3];
            }
#pragma unroll
            for (int mt = 0; mt < 4; mt++)
#pragma unroll
                for (int nt = 0; nt < 2; nt++)
                    mma16816(acc[mt][nt], a[mt], bb[nt]);
        }
        __syncthreads();
    }

    float* C = g_P + ((size_t)(s * BB + b)) * DM * DM;
    const int g = lane >> 2;
    const int t = lane & 3;
#pragma unroll
    for (int mt = 0; mt < 4; mt++) {
        const int r = ti * 128 + wm * 64 + mt * 16 + g;
#pragma unroll
        for (int nt = 0; nt < 2; nt++) {
            const int c = tj * 128 + jh * 64 + wn * 16 + nt * 8 + t * 2;
            *(float2*)(C + (size_t)r * DM + c) =
                make_float2(acc[mt][nt][0], acc[mt][nt][1]);
            *(float2*)(C + (size_t)(r + 8) * DM + c) =
                make_float2(acc[mt][nt][2], acc[mt][nt][3]);
        }
    }
}

// split-K reduce + symmetric mirror, fp16 output
__global__ void reduce_g_kernel()
{
    const int idx = blockIdx.x * 256 + threadIdx.x;
    const int b = idx >> 18;
    const int r = idx & (DM * DM - 1);
    const int i = r >> 9;
    const int j = r & 511;
    if (j < i) return;
    float s = 0.f;
#pragma unroll
    for (int sp = 0; sp < SPLITK; sp++)
        s += g_P[((size_t)(sp * BB + b)) * DM * DM + r];
    __half h = __float2half_rn(s);
    g_Gh[(size_t)b * DM * DM + (size_t)i * DM + j] = h;
    g_Gh[(size_t)b * DM * DM + (size_t)j * DM + i] = h;
}

// mean finish: grid (BB, 4), 512 threads; 4 chunk-groups in parallel,
// deterministic combine.
__global__ void meanx2_kernel()
{
    __shared__ float psum[4][128];
    const int b  = blockIdx.x;
    const int t  = threadIdx.x;
    const int r  = t >> 7;               // chunk group 0..3
    const int jl = t & 127;
    const int j  = blockIdx.y * 128 + jl;
    const float* p = g_Pm + (size_t)b * NCHK * DM + j;
    float s = 0.f;
#pragma unroll 4
    for (int c = r * 32; c < r * 32 + 32; c++)
        s += p[(size_t)c * DM];
    psum[r][jl] = s;
    __syncthreads();
    if (t < 128) {
        float v = (psum[0][t] + psum[1][t]) + (psum[2][t] + psum[3][t]);
        g_xm[b * DM + blockIdx.y * 128 + t] = v * (1.0f / (float)NSEQ);
    }
}

// first[b][j] = xm[b] . Wv[j] for all batches. grid (64), 256 threads.
__global__ void first_kernel(const float* __restrict__ Wv)
{
    __shared__ float xm[BB][DM];
    const int t = threadIdx.x;
    for (int i = t; i < BB * DM; i += 256)
        xm[i >> 9][i & 511] = g_xm[i];
    __syncthreads();

    const int wid  = t >> 5;
    const int lane = t & 31;
    const int j = blockIdx.x * 8 + wid;
    const float* w = Wv + (size_t)j * DM;
    float a0 = 0.f, a1 = 0.f, a2 = 0.f, a3 = 0.f;
    for (int k = lane; k < DM; k += 32) {
        const float wv = w[k];
        a0 += xm[0][k] * wv;
        a1 += xm[1][k] * wv;
        a2 += xm[2][k] * wv;
        a3 += xm[3][k] * wv;
    }
#pragma unroll
    for (int o = 16; o; o >>= 1) {
        a0 += __shfl_xor_sync(0xFFFFFFFFu, a0, o);
        a1 += __shfl_xor_sync(0xFFFFFFFFu, a1, o);
        a2 += __shfl_xor_sync(0xFFFFFFFFu, a2, o);
        a3 += __shfl_xor_sync(0xFFFFFFFFu, a3, o);
    }
    if (lane == 0) {
        g_first[0 * DM + j] = a0;
        g_first[1 * DM + j] = a1;
        g_first[2 * DM + j] = a2;
        g_first[3 * DM + j] = a3;
    }
}

// ============================================================================
// small batched 512^3 GEMM on fp16 HMMA (NT, 128x64 units).
// mode 0: M1[b] = Wvh @ Gh[b]; mode 1: KVt[b] = M1h[b] @ Wth^T.
// grid (4, 8, BB), 256 threads, K = 512 (8 chunks).
// ============================================================================
__global__ void __launch_bounds__(256, 2) small_mma_kernel(int mode)
{
    extern __shared__ char smem[];
    const uint32_t sb = smem_to_u32(smem);
    const int tid  = threadIdx.x;
    const int wid  = tid >> 5;
    const int lane = tid & 31;
    const int wm   = wid >> 2;
    const int wn   = wid & 3;
    const int i0   = blockIdx.x * 128;
    const int j0   = blockIdx.y * 64;
    const int b    = blockIdx.z;
    const size_t bo = (size_t)b * DM * DM;
    const __half* __restrict__ Abase =
        ((mode == 0) ? g_Wvh : (g_M1h + bo)) + (size_t)i0 * DM;
    const __half* __restrict__ Bbase =
        ((mode == 0) ? (g_Gh + bo) : g_Wth) + (size_t)j0 * DM;
    __half* __restrict__ C = ((mode == 0) ? g_M1h : g_KVh) + bo;

    const int a_row = wm * 64 + ((lane >> 3) & 1) * 8 + (lane & 7);
    const int a_byt = ((lane >> 4) & 1) * 16;
    const int b_row = wn * 16 + ((lane >> 4) & 1) * 8 + (lane & 7);
    const int b_byt = ((lane >> 3) & 1) * 16;

    float acc[4][2][4];
#pragma unroll
    for (int mt = 0; mt < 4; mt++)
#pragma unroll
        for (int nt = 0; nt < 2; nt++)
#pragma unroll
            for (int q = 0; q < 4; q++) acc[mt][nt][q] = 0.f;

    NT_STAGE64(Abase, Bbase, DM, 0, 0);

    const int NCH = DM / 64;     // 8
    for (int kc = 0; kc < NCH; kc++) {
        const int cur = kc & 1;
        if (kc + 1 < NCH) {
            NT_STAGE64(Abase, Bbase, DM, kc + 1, cur ^ 1);
            CP_WAIT(1);
        } else {
            CP_WAIT(0);
        }
        __syncthreads();

        const uint32_t abase = sb + SM_A + cur * 16384;
        const uint32_t bbase = sb + SM_B + cur * 8192;
#pragma unroll
        for (int kk = 0; kk < 4; kk++) {
            uint32_t a[4][4], bb[2][2];
#pragma unroll
            for (int mt = 0; mt < 4; mt++) {
                uint32_t off = (uint32_t)((a_row + mt * 16) * 128 + kk * 32 + a_byt);
                ldmx4(a[mt], abase + SW128(off));
            }
            {
                uint32_t off = (uint32_t)(b_row * 128 + kk * 32 + b_byt);
                uint32_t r[4];
                ldmx4(r, bbase + SW128(off));
                bb[0][0] = r[0]; bb[0][1] = r[1];
                bb[1][0] = r[2]; bb[1][1] = r[3];
            }
#pragma unroll
            for (int mt = 0; mt < 4; mt++)
#pragma unroll
                for (int nt = 0; nt < 2; nt++)
                    mma16816(acc[mt][nt], a[mt], bb[nt]);
        }
        __syncthreads();
    }

    const int g = lane >> 2;
    const int t = lane & 3;
#pragma unroll
    for (int mt = 0; mt < 4; mt++) {
        const int r = i0 + wm * 64 + mt * 16 + g;
#pragma unroll
        for (int nt = 0; nt < 2; nt++) {
            const int c = j0 + wn * 16 + nt * 8 + t * 2;
            __half2 h0 = __floats2half2_rn(acc[mt][nt][0], acc[mt][nt][1]);
            __half2 h1 = __floats2half2_rn(acc[mt][nt][2], acc[mt][nt][3]);
            *(__half2*)(C + (size_t)r * DM + c) = h0;
            *(__half2*)(C + (size_t)(r + 8) * DM + c) = h1;
        }
    }
}

// ============================================================================
// final GEMM, fp16 HMMA, 128x64 units:
//   out[m,j] = first[b][j] + scale * sum_k Xh[m,k] KVh[k,j]
// grid (DM/64, MTOT/128) = 2048 CTAs.
// ============================================================================
__global__ void __launch_bounds__(256, 2) final_mma_kernel(float* __restrict__ out)
{
    extern __shared__ char smem[];
    const uint32_t sb = smem_to_u32(smem);
    const int tid  = threadIdx.x;
    const int wid  = tid >> 5;
    const int lane = tid & 31;
    const int wm   = wid >> 2;
    const int wn   = wid & 3;
    const int n0   = blockIdx.x * 64;
    const int m0   = blockIdx.y * 128;
    const int b    = m0 / NSEQ;
    const __half* __restrict__ Abase = g_Xh + (size_t)m0 * DM;
    const __half* __restrict__ Bbase = g_KVh + (size_t)b * DM * DM + (size_t)n0 * DM;

    const int a_row = wm * 64 + ((lane >> 3) & 1) * 8 + (lane & 7);
    const int a_byt = ((lane >> 4) & 1) * 16;
    const int b_row = wn * 16 + ((lane >> 4) & 1) * 8 + (lane & 7);
    const int b_byt = ((lane >> 3) & 1) * 16;

    float acc[4][2][4];
#pragma unroll
    for (int mt = 0; mt < 4; mt++)
#pragma unroll
        for (int nt = 0; nt < 2; nt++)
#pragma unroll
            for (int q = 0; q < 4; q++) acc[mt][nt][q] = 0.f;

    NT_STAGE64(Abase, Bbase, DM, 0, 0);

    for (int kc = 0; kc < 8; kc++) {
        const int cur = kc & 1;
        if (kc + 1 < 8) {
            NT_STAGE64(Abase, Bbase, DM, kc + 1, cur ^ 1);
            CP_WAIT(1);
        } else {
            CP_WAIT(0);
        }
        __syncthreads();

        const uint32_t abase = sb + SM_A + cur * 16384;
        const uint32_t bbase = sb + SM_B + cur * 8192;
#pragma unroll
        for (int kk = 0; kk < 4; kk++) {
            uint32_t a[4][4], bb[2][2];
#pragma unroll
            for (int mt = 0; mt < 4; mt++) {
                uint32_t off = (uint32_t)((a_row + mt * 16) * 128 + kk * 32 + a_byt);
                ldmx4(a[mt], abase + SW128(off));
            }
            {
                uint32_t off = (uint32_t)(b_row * 128 + kk * 32 + b_byt);
                uint32_t r[4];
                ldmx4(r, bbase + SW128(off));
                bb[0][0] = r[0]; bb[0][1] = r[1];
                bb[1][0] = r[2]; bb[1][1] = r[3];
            }
#pragma unroll
            for (int mt = 0; mt < 4; mt++)
#pragma unroll
                for (int nt = 0; nt < 2; nt++)
                    mma16816(acc[mt][nt], a[mt], bb[nt]);
        }
        __syncthreads();
    }

    const float scale = 1.0f / (8192.0f * sqrtf(512.0f));
    const int g = lane >> 2;
    const int t = lane & 3;
#pragma unroll
    for (int mt = 0; mt < 4; mt++) {
        const int r = m0 + wm * 64 + mt * 16 + g;
#pragma unroll
        for (int nt = 0; nt < 2; nt++) {
            const int c = n0 + wn * 16 + nt * 8 + t * 2;
            const float f0 = g_first[b * DM + c];
            const float f1 = g_first[b * DM + c + 1];
            *(float2*)(out + (size_t)r * DM + c) =
                make_float2(f0 + scale * acc[mt][nt][0],
                            f1 + scale * acc[mt][nt][1]);
            *(float2*)(out + (size_t)(r + 8) * DM + c) =
                make_float2(f0 + scale * acc[mt][nt][2],
                            f1 + scale * acc[mt][nt][3]);
        }
    }
}

// ============================================================================
extern "C" void kernel_launch(void* const* d_in, const int* in_sizes, int n_in,
                              void* d_out, int out_size)
{
    (void)in_sizes; (void)n_in; (void)out_size;
    const float* X  = (const float*)d_in[0];
    const float* Wv = (const float*)d_in[1];
    const float* Wt = (const float*)d_in[2];
    float* out = (float*)d_out;

    cudaFuncSetAttribute(final_mma_kernel,
                         cudaFuncAttributeMaxDynamicSharedMemorySize, MMA_SMEM);
    cudaFuncSetAttribute(xtx_mma_kernel,
                         cudaFuncAttributeMaxDynamicSharedMemorySize, MMA_SMEM);
    cudaFuncSetAttribute(small_mma_kernel,
                         cudaFuncAttributeMaxDynamicSharedMemorySize, MMA_SMEM);

    // 0) fp16 conversions (X + transpose + fused column sums; weights)
    convert_x_kernel<<<dim3(NSEQ / 64, DM / 64, BB), 256>>>(X);
    convert_w_kernel<<<dim3(256), 256>>>(Wv, Wt);
    // 1) G[b] = X[b]^T X[b]  (fp16 HMMA, 128x64 units, split-K=16)
    xtx_mma_kernel<<<dim3(20, BB * SPLITK), 256, MMA_SMEM>>>();
    // 2) mean finish + first = mean(X) @ Wv^T
    meanx2_kernel<<<dim3(BB, 4), 512>>>();
    first_kernel<<<dim3(64), 256>>>(Wv);
    // 3) reduce + mirror G -> fp16
    reduce_g_kernel<<<dim3((BB * DM * DM) / 256), 256>>>();
    // 4) M1[b] = Wv @ G[b]; KVt[b] = M1[b] @ Wtheta^T  (fp16 HMMA)
    small_mma_kernel<<<dim3(4, 8, BB), 256, MMA_SMEM>>>(0);
    small_mma_kernel<<<dim3(4, 8, BB), 256, MMA_SMEM>>>(1);
    // 5) out = first + scale * X @ KV   (fp16 HMMA, 128x64 units)
    final_mma_kernel<<<dim3(DM / 64, MTOT / 128), 256, MMA_SMEM>>>(out);
}

// round 15
// speedup vs baseline: 1.0945x; 1.0945x over previous
#include <cuda_runtime.h>
#include <cuda_fp16.h>
#include <math.h>
#include <stdint.h>

#define BB     4
#define NSEQ   8192
#define DM     512
#define MTOT   (BB * NSEQ)       // 32768
#define SPLITK 16
#define KC     (NSEQ / SPLITK)   // 512
#define NCHK   (NSEQ / 64)       // 128 mean partial chunks

// ---------------- scratch (static device memory; referenced ONLY from device
// code — host-side use of these symbols silently hits host memory via ATS) ---
__device__ float g_P  [SPLITK * BB * DM * DM];  // X^T X split-K partials
__device__ float g_Pm [BB * NCHK * DM];         // column-sum partials (fused)
__device__ float g_Pm2[BB * 16 * DM];           // meanx stage-A partials
__device__ float g_first[BB * DM];
__device__ __half g_Xh [(size_t)MTOT * DM];     // fp16 X       [b*n][d]
__device__ __half g_Xt [(size_t)BB * DM * NSEQ];// fp16 X^T     [b][d][n]
__device__ __half g_Gh [BB * DM * DM];          // fp16 G = X^T X (symmetric)
__device__ __half g_M1h[BB * DM * DM];          // fp16 Wv @ G
__device__ __half g_KVh[BB * DM * DM];          // fp16 KV^T    [j][k]
__device__ __half g_Wvh[DM * DM];               // fp16 Wv
__device__ __half g_Wth[DM * DM];               // fp16 Wtheta

__constant__ int c_ti[10] = {0,0,0,0,1,1,1,2,2,3};
__constant__ int c_tj[10] = {0,1,2,3,1,2,3,2,3,3};

#define SW128(x) ((x) ^ (((x) >> 3) & 0x70))

__device__ __forceinline__ uint32_t smem_to_u32(const void* p) {
    uint32_t a;
    asm("{ .reg .u64 t; cvta.to.shared.u64 t, %1; cvt.u32.u64 %0, t; }"
        : "=r"(a) : "l"(p));
    return a;
}
__device__ __forceinline__ void ldmx4(uint32_t r[4], uint32_t addr) {
    asm volatile("ldmatrix.sync.aligned.m8n8.x4.shared.b16 {%0,%1,%2,%3}, [%4];"
        : "=r"(r[0]), "=r"(r[1]), "=r"(r[2]), "=r"(r[3]) : "r"(addr));
}
__device__ __forceinline__ void mma16816(float c[4], const uint32_t a[4],
                                         const uint32_t b[2]) {
    asm volatile("mma.sync.aligned.m16n8k16.row.col.f32.f16.f16.f32 "
        "{%0,%1,%2,%3}, {%4,%5,%6,%7}, {%8,%9}, {%0,%1,%2,%3};"
        : "+f"(c[0]), "+f"(c[1]), "+f"(c[2]), "+f"(c[3])
        : "r"(a[0]), "r"(a[1]), "r"(a[2]), "r"(a[3]), "r"(b[0]), "r"(b[1]));
}
__device__ __forceinline__ void cp_async16(uint32_t dst, const void* src) {
    asm volatile("cp.async.cg.shared.global [%0], [%1], 16;"
        :: "r"(dst), "l"(src) : "memory");
}
#define CP_COMMIT() asm volatile("cp.async.commit_group;" ::: "memory")
#define CP_WAIT(n)  asm volatile("cp.async.wait_group %0;" :: "n"(n) : "memory")

#define SM_A 0                    // 2 bufs x 16384
#define SM_B 32768                // 2 bufs x 16384
#define MMA_SMEM 65536

// generic NT stage (round-13 validated)
#define NT_STAGE(Abase, Bbase, stride, kc, buf) do { \
        _Pragma("unroll") \
        for (int i = tid; i < 2048; i += 256) { \
            const int arr = i >> 10; \
            const int idx = i & 1023; \
            const int row = idx >> 3; \
            const int cg  = idx & 7; \
            const uint32_t sw = SW128((uint32_t)(row * 128 + cg * 16)); \
            const uint32_t dst = sb + (arr ? SM_B : SM_A) + (buf) * 16384 + sw; \
            const __half* src = (arr ? (Bbase) : (Abase)) \
                + (size_t)row * (stride) + (kc) * 64 + cg * 8; \
            cp_async16(dst, src); \
        } \
        CP_COMMIT(); \
    } while (0)

// ============================================================================
// fp16 conversion of X + fused transpose + fused column-sum partials.
// grid (NSEQ/64, DM/64, BB), 256 threads.
// ============================================================================
__global__ void convert_x_kernel(const float* __restrict__ X)
{
    __shared__ __half s[64][72];
    __shared__ float  psum[16][64];
    const int b  = blockIdx.z;
    const int n0 = blockIdx.x * 64;
    const int d0 = blockIdx.y * 64;
    const int t  = threadIdx.x;

    float4 cs = make_float4(0.f, 0.f, 0.f, 0.f);
#pragma unroll
    for (int i = t; i < 1024; i += 256) {
        const int row = i >> 4;
        const int cq  = (i & 15) << 2;
        float4 v = *(const float4*)(X + ((size_t)b * NSEQ + n0 + row) * DM + d0 + cq);
        cs.x += v.x; cs.y += v.y; cs.z += v.z; cs.w += v.w;
        __half h0 = __float2half_rn(v.x), h1 = __float2half_rn(v.y);
        __half h2 = __float2half_rn(v.z), h3 = __float2half_rn(v.w);
        uint2 u; __half* ph = (__half*)&u;
        ph[0] = h0; ph[1] = h1; ph[2] = h2; ph[3] = h3;
        *(uint2*)(g_Xh + ((size_t)b * NSEQ + n0 + row) * DM + d0 + cq) = u;
        s[cq + 0][row] = h0; s[cq + 1][row] = h1;
        s[cq + 2][row] = h2; s[cq + 3][row] = h3;
    }
    *(float4*)&psum[t >> 4][(t & 15) << 2] = cs;
    __syncthreads();

#pragma unroll
    for (int i = t; i < 1024; i += 256) {
        const int dr = i >> 4;
        const int nq = (i & 15) << 2;
        uint2 u; __half* ph = (__half*)&u;
        ph[0] = s[dr][nq]; ph[1] = s[dr][nq + 1];
        ph[2] = s[dr][nq + 2]; ph[3] = s[dr][nq + 3];
        *(uint2*)(g_Xt + ((size_t)b * DM + d0 + dr) * NSEQ + n0 + nq) = u;
    }

    if (t < 64) {
        float v = 0.f;
#pragma unroll
        for (int rg = 0; rg < 16; rg++) v += psum[rg][t];
        g_Pm[((size_t)b * NCHK + blockIdx.x) * DM + d0 + t] = v;
    }
}

// fp16 conversion of Wv / Wtheta. grid 256, 256 thr.
__global__ void convert_w_kernel(const float* __restrict__ Wv,
                                 const float* __restrict__ Wt)
{
    const int blk = blockIdx.x;
    const float* src = (blk < 128) ? Wv : Wt;
    __half* dst = (blk < 128) ? g_Wvh : g_Wth;
    const size_t base = ((size_t)(blk & 127) * 256 + threadIdx.x) * 8;
    float4 v0 = *(const float4*)(src + base);
    float4 v1 = *(const float4*)(src + base + 4);
    uint4 u; __half* ph = (__half*)&u;
    ph[0] = __float2half_rn(v0.x); ph[1] = __float2half_rn(v0.y);
    ph[2] = __float2half_rn(v0.z); ph[3] = __float2half_rn(v0.w);
    ph[4] = __float2half_rn(v1.x); ph[5] = __float2half_rn(v1.y);
    ph[6] = __float2half_rn(v1.z); ph[7] = __float2half_rn(v1.w);
    *(uint4*)(dst + base) = u;
}

// ============================================================================
// X^T X on fp16 HMMA (round-13 validated 128x128 tiles):
// grid (10, BB*SPLITK), 256 threads, K = 512 per CTA (8 chunks of 64).
// ============================================================================
__global__ void __launch_bounds__(256, 2) xtx_mma_kernel()
{
    extern __shared__ char smem[];
    const uint32_t sb = smem_to_u32(smem);
    const int tid  = threadIdx.x;
    const int wid  = tid >> 5;
    const int lane = tid & 31;
    const int wm   = wid >> 2;
    const int wn   = wid & 3;
    const int ti   = c_ti[blockIdx.x];
    const int tj   = c_tj[blockIdx.x];
    const int b    = blockIdx.y / SPLITK;
    const int s    = blockIdx.y % SPLITK;
    const __half* __restrict__ Abase =
        g_Xt + ((size_t)b * DM + ti * 128) * NSEQ + (size_t)s * KC;
    const __half* __restrict__ Bbase =
        g_Xt + ((size_t)b * DM + tj * 128) * NSEQ + (size_t)s * KC;

    const int a_row = wm * 64 + ((lane >> 3) & 1) * 8 + (lane & 7);
    const int a_byt = ((lane >> 4) & 1) * 16;
    const int b_row = wn * 32 + ((lane >> 4) & 1) * 8 + (lane & 7);
    const int b_byt = ((lane >> 3) & 1) * 16;

    float acc[4][4][4];
#pragma unroll
    for (int mt = 0; mt < 4; mt++)
#pragma unroll
        for (int nt = 0; nt < 4; nt++)
#pragma unroll
            for (int q = 0; q < 4; q++) acc[mt][nt][q] = 0.f;

    NT_STAGE(Abase, Bbase, NSEQ, 0, 0);

    const int NCH = KC / 64;     // 8
    for (int kc = 0; kc < NCH; kc++) {
        const int cur = kc & 1;
        if (kc + 1 < NCH) {
            NT_STAGE(Abase, Bbase, NSEQ, kc + 1, cur ^ 1);
            CP_WAIT(1);
        } else {
            CP_WAIT(0);
        }
        __syncthreads();

        const uint32_t abase = sb + SM_A + cur * 16384;
        const uint32_t bbase = sb + SM_B + cur * 16384;
#pragma unroll
        for (int kk = 0; kk < 4; kk++) {
            uint32_t a[4][4], bb[4][2];
#pragma unroll
            for (int mt = 0; mt < 4; mt++) {
                uint32_t off = (uint32_t)((a_row + mt * 16) * 128 + kk * 32 + a_byt);
                ldmx4(a[mt], abase + SW128(off));
            }
#pragma unroll
            for (int p = 0; p < 2; p++) {
                uint32_t off = (uint32_t)((b_row + p * 16) * 128 + kk * 32 + b_byt);
                uint32_t r[4];
                ldmx4(r, bbase + SW128(off));
                bb[p * 2][0] = r[0]; bb[p * 2][1] = r[1];
                bb[p * 2 + 1][0] = r[2]; bb[p * 2 + 1][1] = r[3];
            }
#pragma unroll
            for (int mt = 0; mt < 4; mt++)
#pragma unroll
                for (int nt = 0; nt < 4; nt++)
                    mma16816(acc[mt][nt], a[mt], bb[nt]);
        }
        __syncthreads();
    }

    float* C = g_P + ((size_t)(s * BB + b)) * DM * DM;
    const int g = lane >> 2;
    const int t = lane & 3;
#pragma unroll
    for (int mt = 0; mt < 4; mt++) {
        const int r = ti * 128 + wm * 64 + mt * 16 + g;
#pragma unroll
        for (int nt = 0; nt < 4; nt++) {
            const int c = tj * 128 + wn * 32 + nt * 8 + t * 2;
            *(float2*)(C + (size_t)r * DM + c) =
                make_float2(acc[mt][nt][0], acc[mt][nt][1]);
            *(float2*)(C + (size_t)(r + 8) * DM + c) =
                make_float2(acc[mt][nt][2], acc[mt][nt][3]);
        }
    }
}

// split-K reduce + symmetric mirror, fp16 output
__global__ void reduce_g_kernel()
{
    const int idx = blockIdx.x * 256 + threadIdx.x;
    const int b = idx >> 18;
    const int r = idx & (DM * DM - 1);
    const int i = r >> 9;
    const int j = r & 511;
    if (j < i) return;
    float s = 0.f;
#pragma unroll
    for (int sp = 0; sp < SPLITK; sp++)
        s += g_P[((size_t)(sp * BB + b)) * DM * DM + r];
    __half h = __float2half_rn(s);
    g_Gh[(size_t)b * DM * DM + (size_t)i * DM + j] = h;
    g_Gh[(size_t)b * DM * DM + (size_t)j * DM + i] = h;
}

// mean stage A: grid (BB, 4, 16), 128 threads; block sums 8 chunks.
__global__ void meanx2_kernel()
{
    const int b  = blockIdx.x;
    const int j  = blockIdx.y * 128 + threadIdx.x;
    const int sg = blockIdx.z;                         // 0..15 (8 chunks each)
    const float* p = g_Pm + ((size_t)b * NCHK + sg * 8) * DM + j;
    float s0 = 0.f, s1 = 0.f, s2 = 0.f, s3 = 0.f;
    s0 = p[0 * DM]; s1 = p[1 * DM]; s2 = p[2 * DM]; s3 = p[3 * DM];
    s0 += p[4 * DM]; s1 += p[5 * DM]; s2 += p[6 * DM]; s3 += p[7 * DM];
    g_Pm2[((size_t)b * 16 + sg) * DM + j] = (s0 + s1) + (s2 + s3);
}

// first[b][j] = xm[b] . Wv[j] for all batches; xm built from 16 stage-A
// partials (fixed order). grid (64), 256 threads.
__global__ void first_kernel(const float* __restrict__ Wv)
{
    __shared__ float xm[BB][DM];
    const int t = threadIdx.x;
    for (int i = t; i < BB * DM; i += 256) {
        const int b = i >> 9;
        const int d = i & 511;
        float s = 0.f;
#pragma unroll
        for (int k = 0; k < 16; k++)
            s += g_Pm2[((size_t)b * 16 + k) * DM + d];
        xm[b][d] = s * (1.0f / (float)NSEQ);
    }
    __syncthreads();

    const int wid  = t >> 5;
    const int lane = t & 31;
    const int j = blockIdx.x * 8 + wid;
    const float* w = Wv + (size_t)j * DM;
    float a0 = 0.f, a1 = 0.f, a2 = 0.f, a3 = 0.f;
    for (int k = lane; k < DM; k += 32) {
        const float wv = w[k];
        a0 += xm[0][k] * wv;
        a1 += xm[1][k] * wv;
        a2 += xm[2][k] * wv;
        a3 += xm[3][k] * wv;
    }
#pragma unroll
    for (int o = 16; o; o >>= 1) {
        a0 += __shfl_xor_sync(0xFFFFFFFFu, a0, o);
        a1 += __shfl_xor_sync(0xFFFFFFFFu, a1, o);
        a2 += __shfl_xor_sync(0xFFFFFFFFu, a2, o);
        a3 += __shfl_xor_sync(0xFFFFFFFFu, a3, o);
    }
    if (lane == 0) {
        g_first[0 * DM + j] = a0;
        g_first[1 * DM + j] = a1;
        g_first[2 * DM + j] = a2;
        g_first[3 * DM + j] = a3;
    }
}

// ============================================================================
// small batched 512^3 GEMM on fp16 HMMA (round-13 config).
// mode 0: M1[b] = Wvh @ Gh[b]; mode 1: KVt[b] = M1h[b] @ Wth^T.
// grid (4, 4, BB), 256 threads, K = 512 (8 chunks).
// ============================================================================
__global__ void __launch_bounds__(256, 2) small_mma_kernel(int mode)
{
    extern __shared__ char smem[];
    const uint32_t sb = smem_to_u32(smem);
    const int tid  = threadIdx.x;
    const int wid  = tid >> 5;
    const int lane = tid & 31;
    const int wm   = wid >> 2;
    const int wn   = wid & 3;
    const int i0   = blockIdx.x * 128;
    const int j0   = blockIdx.y * 128;
    const int b    = blockIdx.z;
    const size_t bo = (size_t)b * DM * DM;
    const __half* __restrict__ Abase =
        ((mode == 0) ? g_Wvh : (g_M1h + bo)) + (size_t)i0 * DM;
    const __half* __restrict__ Bbase =
        ((mode == 0) ? (g_Gh + bo) : g_Wth) + (size_t)j0 * DM;
    __half* __restrict__ C = ((mode == 0) ? g_M1h : g_KVh) + bo;

    const int a_row = wm * 64 + ((lane >> 3) & 1) * 8 + (lane & 7);
    const int a_byt = ((lane >> 4) & 1) * 16;
    const int b_row = wn * 32 + ((lane >> 4) & 1) * 8 + (lane & 7);
    const int b_byt = ((lane >> 3) & 1) * 16;

    float acc[4][4][4];
#pragma unroll
    for (int mt = 0; mt < 4; mt++)
#pragma unroll
        for (int nt = 0; nt < 4; nt++)
#pragma unroll
            for (int q = 0; q < 4; q++) acc[mt][nt][q] = 0.f;

    NT_STAGE(Abase, Bbase, DM, 0, 0);

    const int NCH = DM / 64;     // 8
    for (int kc = 0; kc < NCH; kc++) {
        const int cur = kc & 1;
        if (kc + 1 < NCH) {
            NT_STAGE(Abase, Bbase, DM, kc + 1, cur ^ 1);
            CP_WAIT(1);
        } else {
            CP_WAIT(0);
        }
        __syncthreads();

        const uint32_t abase = sb + SM_A + cur * 16384;
        const uint32_t bbase = sb + SM_B + cur * 16384;
#pragma unroll
        for (int kk = 0; kk < 4; kk++) {
            uint32_t a[4][4], bb[4][2];
#pragma unroll
            for (int mt = 0; mt < 4; mt++) {
                uint32_t off = (uint32_t)((a_row + mt * 16) * 128 + kk * 32 + a_byt);
                ldmx4(a[mt], abase + SW128(off));
            }
#pragma unroll
            for (int p = 0; p < 2; p++) {
                uint32_t off = (uint32_t)((b_row + p * 16) * 128 + kk * 32 + b_byt);
                uint32_t r[4];
                ldmx4(r, bbase + SW128(off));
                bb[p * 2][0] = r[0]; bb[p * 2][1] = r[1];
                bb[p * 2 + 1][0] = r[2]; bb[p * 2 + 1][1] = r[3];
            }
#pragma unroll
            for (int mt = 0; mt < 4; mt++)
#pragma unroll
                for (int nt = 0; nt < 4; nt++)
                    mma16816(acc[mt][nt], a[mt], bb[nt]);
        }
        __syncthreads();
    }

    const int g = lane >> 2;
    const int t = lane & 3;
#pragma unroll
    for (int mt = 0; mt < 4; mt++) {
        const int r = i0 + wm * 64 + mt * 16 + g;
#pragma unroll
        for (int nt = 0; nt < 4; nt++) {
            const int c = j0 + wn * 32 + nt * 8 + t * 2;
            __half2 h0 = __floats2half2_rn(acc[mt][nt][0], acc[mt][nt][1]);
            __half2 h1 = __floats2half2_rn(acc[mt][nt][2], acc[mt][nt][3]);
            *(__half2*)(C + (size_t)r * DM + c) = h0;
            *(__half2*)(C + (size_t)(r + 8) * DM + c) = h1;
        }
    }
}

// ============================================================================
// final GEMM, single-pass fp16 HMMA (round-13 config):
//   out[m,j] = first[b][j] + scale * sum_k Xh[m,k] KVh[k,j]
// grid (DM/128, MTOT/128), 256 threads.
// ============================================================================
__global__ void __launch_bounds__(256, 2) final_mma_kernel(float* __restrict__ out)
{
    extern __shared__ char smem[];
    const uint32_t sb = smem_to_u32(smem);
    const int tid  = threadIdx.x;
    const int wid  = tid >> 5;
    const int lane = tid & 31;
    const int wm   = wid >> 2;
    const int wn   = wid & 3;
    const int n0   = blockIdx.x * 128;
    const int m0   = blockIdx.y * 128;
    const int b    = m0 / NSEQ;
    const __half* __restrict__ Abase = g_Xh + (size_t)m0 * DM;
    const __half* __restrict__ Bbase = g_KVh + (size_t)b * DM * DM + (size_t)n0 * DM;

    const int a_row = wm * 64 + ((lane >> 3) & 1) * 8 + (lane & 7);
    const int a_byt = ((lane >> 4) & 1) * 16;
    const int b_row = wn * 32 + ((lane >> 4) & 1) * 8 + (lane & 7);
    const int b_byt = ((lane >> 3) & 1) * 16;

    float acc[4][4][4];
#pragma unroll
    for (int mt = 0; mt < 4; mt++)
#pragma unroll
        for (int nt = 0; nt < 4; nt++)
#pragma unroll
            for (int q = 0; q < 4; q++) acc[mt][nt][q] = 0.f;

    NT_STAGE(Abase, Bbase, DM, 0, 0);

    for (int kc = 0; kc < 8; kc++) {
        const int cur = kc & 1;
        if (kc + 1 < 8) {
            NT_STAGE(Abase, Bbase, DM, kc + 1, cur ^ 1);
            CP_WAIT(1);
        } else {
            CP_WAIT(0);
        }
        __syncthreads();

        const uint32_t abase = sb + SM_A + cur * 16384;
        const uint32_t bbase = sb + SM_B + cur * 16384;
#pragma unroll
        for (int kk = 0; kk < 4; kk++) {
            uint32_t a[4][4], bb[4][2];
#pragma unroll
            for (int mt = 0; mt < 4; mt++) {
                uint32_t off = (uint32_t)((a_row + mt * 16) * 128 + kk * 32 + a_byt);
                ldmx4(a[mt], abase + SW128(off));
            }
#pragma unroll
            for (int p = 0; p < 2; p++) {
                uint32_t off = (uint32_t)((b_row + p * 16) * 128 + kk * 32 + b_byt);
                uint32_t r[4];
                ldmx4(r, bbase + SW128(off));
                bb[p * 2][0] = r[0]; bb[p * 2][1] = r[1];
                bb[p * 2 + 1][0] = r[2]; bb[p * 2 + 1][1] = r[3];
            }
#pragma unroll
            for (int mt = 0; mt < 4; mt++)
#pragma unroll
                for (int nt = 0; nt < 4; nt++)
                    mma16816(acc[mt][nt], a[mt], bb[nt]);
        }
        __syncthreads();
    }

    const float scale = 1.0f / (8192.0f * sqrtf(512.0f));
    const int g = lane >> 2;
    const int t = lane & 3;
#pragma unroll
    for (int mt = 0; mt < 4; mt++) {
        const int r = m0 + wm * 64 + mt * 16 + g;
#pragma unroll
        for (int nt = 0; nt < 4; nt++) {
            const int c = n0 + wn * 32 + nt * 8 + t * 2;
            const float f0 = g_first[b * DM + c];
            const float f1 = g_first[b * DM + c + 1];
            *(float2*)(out + (size_t)r * DM + c) =
                make_float2(f0 + scale * acc[mt][nt][0],
                            f1 + scale * acc[mt][nt][1]);
            *(float2*)(out + (size_t)(r + 8) * DM + c) =
                make_float2(f0 + scale * acc[mt][nt][2],
                            f1 + scale * acc[mt][nt][3]);
        }
    }
}

// ============================================================================
extern "C" void kernel_launch(void* const* d_in, const int* in_sizes, int n_in,
                              void* d_out, int out_size)
{
    (void)in_sizes; (void)n_in; (void)out_size;
    const float* X  = (const float*)d_in[0];
    const float* Wv = (const float*)d_in[1];
    const float* Wt = (const float*)d_in[2];
    float* out = (float*)d_out;

    cudaFuncSetAttribute(final_mma_kernel,
                         cudaFuncAttributeMaxDynamicSharedMemorySize, MMA_SMEM);
    cudaFuncSetAttribute(xtx_mma_kernel,
                         cudaFuncAttributeMaxDynamicSharedMemorySize, MMA_SMEM);
    cudaFuncSetAttribute(small_mma_kernel,
                         cudaFuncAttributeMaxDynamicSharedMemorySize, MMA_SMEM);

    // 0) fp16 conversions (X + transpose + fused column sums; weights)
    convert_x_kernel<<<dim3(NSEQ / 64, DM / 64, BB), 256>>>(X);
    convert_w_kernel<<<dim3(256), 256>>>(Wv, Wt);
    // 1) G[b] = X[b]^T X[b]  (fp16 HMMA, 128x128 tiles, split-K=16)
    xtx_mma_kernel<<<dim3(10, BB * SPLITK), 256, MMA_SMEM>>>();
    // 2) mean stage A (wide) + first = mean(X) @ Wv^T (stage B folded in)
    meanx2_kernel<<<dim3(BB, 4, 16), 128>>>();
    first_kernel<<<dim3(64), 256>>>(Wv);
    // 3) reduce + mirror G -> fp16
    reduce_g_kernel<<<dim3((BB * DM * DM) / 256), 256>>>();
    // 4) M1[b] = Wv @ G[b]; KVt[b] = M1[b] @ Wtheta^T  (fp16 HMMA)
    small_mma_kernel<<<dim3(4, 4, BB), 256, MMA_SMEM>>>(0);
    small_mma_kernel<<<dim3(4, 4, BB), 256, MMA_SMEM>>>(1);
    // 5) out = first + scale * X @ KV   (fp16 HMMA)
    final_mma_kernel<<<dim3(DM / 128, MTOT / 128), 256, MMA_SMEM>>>(out);
}

// round 16
// speedup vs baseline: 1.1488x; 1.0496x over previous
#include <cuda_runtime.h>
#include <cuda_fp16.h>
#include <math.h>
#include <stdint.h>

#define BB     4
#define NSEQ   8192
#define DM     512
#define MTOT   (BB * NSEQ)       // 32768
#define SPLITK 16
#define KC     (NSEQ / SPLITK)   // 512
#define NCHK   (NSEQ / 64)       // 128 mean partial chunks

// ---------------- scratch (static device memory; referenced ONLY from device
// code — host-side use of these symbols silently hits host memory via ATS) ---
__device__ float g_P  [SPLITK * BB * DM * DM];  // X^T X split-K partials
__device__ float g_Pm [BB * NCHK * DM];         // column-sum partials (fused)
__device__ float g_Pm2[BB * 16 * DM];           // meanx stage-A partials
__device__ float g_first[BB * DM];
__device__ __half g_Xh [(size_t)MTOT * DM];     // fp16 X       [b*n][d]
__device__ __half g_Xt [(size_t)BB * DM * NSEQ];// fp16 X^T     [b][d][n]
__device__ __half g_Gh [BB * DM * DM];          // fp16 G = X^T X (symmetric)
__device__ __half g_M1h[BB * DM * DM];          // fp16 Wv @ G
__device__ __half g_KVh[BB * DM * DM];          // fp16 KV^T    [j][k]
__device__ __half g_Wvh[DM * DM];               // fp16 Wv
__device__ __half g_Wth[DM * DM];               // fp16 Wtheta

__constant__ int c_ti[10] = {0,0,0,0,1,1,1,2,2,3};
__constant__ int c_tj[10] = {0,1,2,3,1,2,3,2,3,3};

#define SW128(x) ((x) ^ (((x) >> 3) & 0x70))

__device__ __forceinline__ uint32_t smem_to_u32(const void* p) {
    uint32_t a;
    asm("{ .reg .u64 t; cvta.to.shared.u64 t, %1; cvt.u32.u64 %0, t; }"
        : "=r"(a) : "l"(p));
    return a;
}
__device__ __forceinline__ void ldmx4(uint32_t r[4], uint32_t addr) {
    asm volatile("ldmatrix.sync.aligned.m8n8.x4.shared.b16 {%0,%1,%2,%3}, [%4];"
        : "=r"(r[0]), "=r"(r[1]), "=r"(r[2]), "=r"(r[3]) : "r"(addr));
}
__device__ __forceinline__ void mma16816(float c[4], const uint32_t a[4],
                                         const uint32_t b[2]) {
    asm volatile("mma.sync.aligned.m16n8k16.row.col.f32.f16.f16.f32 "
        "{%0,%1,%2,%3}, {%4,%5,%6,%7}, {%8,%9}, {%0,%1,%2,%3};"
        : "+f"(c[0]), "+f"(c[1]), "+f"(c[2]), "+f"(c[3])
        : "r"(a[0]), "r"(a[1]), "r"(a[2]), "r"(a[3]), "r"(b[0]), "r"(b[1]));
}
__device__ __forceinline__ void cp_async16(uint32_t dst, const void* src) {
    asm volatile("cp.async.cg.shared.global [%0], [%1], 16;"
        :: "r"(dst), "l"(src) : "memory");
}
#define CP_COMMIT() asm volatile("cp.async.commit_group;" ::: "memory")
#define CP_WAIT(n)  asm volatile("cp.async.wait_group %0;" :: "n"(n) : "memory")

#define SM_A 0                    // 2 bufs x 16384
#define SM_B 32768                // 2 bufs x 16384
#define MMA_SMEM 65536

// generic NT stage (128x128 tiles, round-13 validated)
#define NT_STAGE(Abase, Bbase, stride, kc, buf) do { \
        _Pragma("unroll") \
        for (int i = tid; i < 2048; i += 256) { \
            const int arr = i >> 10; \
            const int idx = i & 1023; \
            const int row = idx >> 3; \
            const int cg  = idx & 7; \
            const uint32_t sw = SW128((uint32_t)(row * 128 + cg * 16)); \
            const uint32_t dst = sb + (arr ? SM_B : SM_A) + (buf) * 16384 + sw; \
            const __half* src = (arr ? (Bbase) : (Abase)) \
                + (size_t)row * (stride) + (kc) * 64 + cg * 8; \
            cp_async16(dst, src); \
        } \
        CP_COMMIT(); \
    } while (0)

// 64x64 tile stage: A 64 rows + B 64 rows, 1024 f16x8 slots
#define SM64_A 0                  // 2 bufs x 8192
#define SM64_B 16384              // 2 bufs x 8192
#define SMALL_SMEM 32768
#define NT_STAGE64(Abase, Bbase, stride, kc, buf) do { \
        _Pragma("unroll") \
        for (int i = tid; i < 1024; i += 256) { \
            const int arr = i >> 9; \
            const int idx = i & 511; \
            const int row = idx >> 3; \
            const int cg  = idx & 7; \
            const uint32_t sw = SW128((uint32_t)(row * 128 + cg * 16)); \
            const uint32_t dst = sb + (arr ? SM64_B : SM64_A) + (buf) * 8192 + sw; \
            const __half* src = (arr ? (Bbase) : (Abase)) \
                + (size_t)row * (stride) + (kc) * 64 + cg * 8; \
            cp_async16(dst, src); \
        } \
        CP_COMMIT(); \
    } while (0)

// ============================================================================
// fp16 conversion of X + fused transpose + fused column-sum partials,
// with Wv/Wtheta conversion folded in as the z==BB slab.
// grid (NSEQ/64, DM/64, BB+1), 256 threads.
// ============================================================================
__global__ void convert_x_kernel(const float* __restrict__ X,
                                 const float* __restrict__ Wv,
                                 const float* __restrict__ Wt)
{
    if (blockIdx.z == BB) {
        if (blockIdx.y >= 2) return;               // 256 weight blocks
        const int blk = blockIdx.y * 128 + blockIdx.x;
        const float* src = (blk < 128) ? Wv : Wt;
        __half* dst = (blk < 128) ? g_Wvh : g_Wth;
        const size_t base = ((size_t)(blk & 127) * 256 + threadIdx.x) * 8;
        float4 v0 = *(const float4*)(src + base);
        float4 v1 = *(const float4*)(src + base + 4);
        uint4 u; __half* ph = (__half*)&u;
        ph[0] = __float2half_rn(v0.x); ph[1] = __float2half_rn(v0.y);
        ph[2] = __float2half_rn(v0.z); ph[3] = __float2half_rn(v0.w);
        ph[4] = __float2half_rn(v1.x); ph[5] = __float2half_rn(v1.y);
        ph[6] = __float2half_rn(v1.z); ph[7] = __float2half_rn(v1.w);
        *(uint4*)(dst + base) = u;
        return;
    }

    __shared__ __half s[64][72];
    __shared__ float  psum[16][64];
    const int b  = blockIdx.z;
    const int n0 = blockIdx.x * 64;
    const int d0 = blockIdx.y * 64;
    const int t  = threadIdx.x;

    float4 cs = make_float4(0.f, 0.f, 0.f, 0.f);
#pragma unroll
    for (int i = t; i < 1024; i += 256) {
        const int row = i >> 4;
        const int cq  = (i & 15) << 2;
        float4 v = *(const float4*)(X + ((size_t)b * NSEQ + n0 + row) * DM + d0 + cq);
        cs.x += v.x; cs.y += v.y; cs.z += v.z; cs.w += v.w;
        __half h0 = __float2half_rn(v.x), h1 = __float2half_rn(v.y);
        __half h2 = __float2half_rn(v.z), h3 = __float2half_rn(v.w);
        uint2 u; __half* ph = (__half*)&u;
        ph[0] = h0; ph[1] = h1; ph[2] = h2; ph[3] = h3;
        *(uint2*)(g_Xh + ((size_t)b * NSEQ + n0 + row) * DM + d0 + cq) = u;
        s[cq + 0][row] = h0; s[cq + 1][row] = h1;
        s[cq + 2][row] = h2; s[cq + 3][row] = h3;
    }
    *(float4*)&psum[t >> 4][(t & 15) << 2] = cs;
    __syncthreads();

#pragma unroll
    for (int i = t; i < 1024; i += 256) {
        const int dr = i >> 4;
        const int nq = (i & 15) << 2;
        uint2 u; __half* ph = (__half*)&u;
        ph[0] = s[dr][nq]; ph[1] = s[dr][nq + 1];
        ph[2] = s[dr][nq + 2]; ph[3] = s[dr][nq + 3];
        *(uint2*)(g_Xt + ((size_t)b * DM + d0 + dr) * NSEQ + n0 + nq) = u;
    }

    if (t < 64) {
        float v = 0.f;
#pragma unroll
        for (int rg = 0; rg < 16; rg++) v += psum[rg][t];
        g_Pm[((size_t)b * NCHK + blockIdx.x) * DM + d0 + t] = v;
    }
}

// ============================================================================
// X^T X on fp16 HMMA (128x128 tiles): grid (10, BB*SPLITK), 256 threads.
// ============================================================================
__global__ void __launch_bounds__(256, 2) xtx_mma_kernel()
{
    extern __shared__ char smem[];
    const uint32_t sb = smem_to_u32(smem);
    const int tid  = threadIdx.x;
    const int wid  = tid >> 5;
    const int lane = tid & 31;
    const int wm   = wid >> 2;
    const int wn   = wid & 3;
    const int ti   = c_ti[blockIdx.x];
    const int tj   = c_tj[blockIdx.x];
    const int b    = blockIdx.y / SPLITK;
    const int s    = blockIdx.y % SPLITK;
    const __half* __restrict__ Abase =
        g_Xt + ((size_t)b * DM + ti * 128) * NSEQ + (size_t)s * KC;
    const __half* __restrict__ Bbase =
        g_Xt + ((size_t)b * DM + tj * 128) * NSEQ + (size_t)s * KC;

    const int a_row = wm * 64 + ((lane >> 3) & 1) * 8 + (lane & 7);
    const int a_byt = ((lane >> 4) & 1) * 16;
    const int b_row = wn * 32 + ((lane >> 4) & 1) * 8 + (lane & 7);
    const int b_byt = ((lane >> 3) & 1) * 16;

    float acc[4][4][4];
#pragma unroll
    for (int mt = 0; mt < 4; mt++)
#pragma unroll
        for (int nt = 0; nt < 4; nt++)
#pragma unroll
            for (int q = 0; q < 4; q++) acc[mt][nt][q] = 0.f;

    NT_STAGE(Abase, Bbase, NSEQ, 0, 0);

    const int NCH = KC / 64;     // 8
    for (int kc = 0; kc < NCH; kc++) {
        const int cur = kc & 1;
        if (kc + 1 < NCH) {
            NT_STAGE(Abase, Bbase, NSEQ, kc + 1, cur ^ 1);
            CP_WAIT(1);
        } else {
            CP_WAIT(0);
        }
        __syncthreads();

        const uint32_t abase = sb + SM_A + cur * 16384;
        const uint32_t bbase = sb + SM_B + cur * 16384;
#pragma unroll
        for (int kk = 0; kk < 4; kk++) {
            uint32_t a[4][4], bb[4][2];
#pragma unroll
            for (int mt = 0; mt < 4; mt++) {
                uint32_t off = (uint32_t)((a_row + mt * 16) * 128 + kk * 32 + a_byt);
                ldmx4(a[mt], abase + SW128(off));
            }
#pragma unroll
            for (int p = 0; p < 2; p++) {
                uint32_t off = (uint32_t)((b_row + p * 16) * 128 + kk * 32 + b_byt);
                uint32_t r[4];
                ldmx4(r, bbase + SW128(off));
                bb[p * 2][0] = r[0]; bb[p * 2][1] = r[1];
                bb[p * 2 + 1][0] = r[2]; bb[p * 2 + 1][1] = r[3];
            }
#pragma unroll
            for (int mt = 0; mt < 4; mt++)
#pragma unroll
                for (int nt = 0; nt < 4; nt++)
                    mma16816(acc[mt][nt], a[mt], bb[nt]);
        }
        __syncthreads();
    }

    float* C = g_P + ((size_t)(s * BB + b)) * DM * DM;
    const int g = lane >> 2;
    const int t = lane & 3;
#pragma unroll
    for (int mt = 0; mt < 4; mt++) {
        const int r = ti * 128 + wm * 64 + mt * 16 + g;
#pragma unroll
        for (int nt = 0; nt < 4; nt++) {
            const int c = tj * 128 + wn * 32 + nt * 8 + t * 2;
            *(float2*)(C + (size_t)r * DM + c) =
                make_float2(acc[mt][nt][0], acc[mt][nt][1]);
            *(float2*)(C + (size_t)(r + 8) * DM + c) =
                make_float2(acc[mt][nt][2], acc[mt][nt][3]);
        }
    }
}

// ============================================================================
// split-K reduce + symmetric mirror (fp16 out), with meanx stage A folded
// into blocks >= 4096. grid (4096 + 64), 256 threads.
// ============================================================================
__global__ void reduce_g_kernel()
{
    const int blk = blockIdx.x;
    if (blk >= 4096) {
        // meanx stage A: 64 blocks; block m -> (b = m>>4, sg = m&15)
        const int m  = blk - 4096;
        const int b  = m >> 4;
        const int sg = m & 15;
        for (int j = threadIdx.x; j < DM; j += 256) {
            const float* p = g_Pm + ((size_t)b * NCHK + sg * 8) * DM + j;
            float s0 = p[0 * DM] + p[4 * DM];
            float s1 = p[1 * DM] + p[5 * DM];
            float s2 = p[2 * DM] + p[6 * DM];
            float s3 = p[3 * DM] + p[7 * DM];
            g_Pm2[((size_t)b * 16 + sg) * DM + j] = (s0 + s1) + (s2 + s3);
        }
        return;
    }
    const int idx = blk * 256 + threadIdx.x;
    const int b = idx >> 18;
    const int r = idx & (DM * DM - 1);
    const int i = r >> 9;
    const int j = r & 511;
    if (j < i) return;
    float s = 0.f;
#pragma unroll
    for (int sp = 0; sp < SPLITK; sp++)
        s += g_P[((size_t)(sp * BB + b)) * DM * DM + r];
    __half h = __float2half_rn(s);
    g_Gh[(size_t)b * DM * DM + (size_t)i * DM + j] = h;
    g_Gh[(size_t)b * DM * DM + (size_t)j * DM + i] = h;
}

// first[b][j] = xm[b] . Wv[j] for all batches; xm built from 16 stage-A
// partials (fixed order). grid (64), 256 threads.
__global__ void first_kernel(const float* __restrict__ Wv)
{
    __shared__ float xm[BB][DM];
    const int t = threadIdx.x;
    for (int i = t; i < BB * DM; i += 256) {
        const int b = i >> 9;
        const int d = i & 511;
        float s = 0.f;
#pragma unroll
        for (int k = 0; k < 16; k++)
            s += g_Pm2[((size_t)b * 16 + k) * DM + d];
        xm[b][d] = s * (1.0f / (float)NSEQ);
    }
    __syncthreads();

    const int wid  = t >> 5;
    const int lane = t & 31;
    const int j = blockIdx.x * 8 + wid;
    const float* w = Wv + (size_t)j * DM;
    float a0 = 0.f, a1 = 0.f, a2 = 0.f, a3 = 0.f;
    for (int k = lane; k < DM; k += 32) {
        const float wv = w[k];
        a0 += xm[0][k] * wv;
        a1 += xm[1][k] * wv;
        a2 += xm[2][k] * wv;
        a3 += xm[3][k] * wv;
    }
#pragma unroll
    for (int o = 16; o; o >>= 1) {
        a0 += __shfl_xor_sync(0xFFFFFFFFu, a0, o);
        a1 += __shfl_xor_sync(0xFFFFFFFFu, a1, o);
        a2 += __shfl_xor_sync(0xFFFFFFFFu, a2, o);
        a3 += __shfl_xor_sync(0xFFFFFFFFu, a3, o);
    }
    if (lane == 0) {
        g_first[0 * DM + j] = a0;
        g_first[1 * DM + j] = a1;
        g_first[2 * DM + j] = a2;
        g_first[3 * DM + j] = a3;
    }
}

// ============================================================================
// small batched 512^3 GEMM on fp16 HMMA, 64x64 tiles (latency-optimized).
// mode 0: M1[b] = Wvh @ Gh[b]; mode 1: KVt[b] = M1h[b] @ Wth^T.
// grid (8, 8, BB) = 256 CTAs, 256 threads; warps 2(M=32) x 4(N=16).
// ============================================================================
__global__ void __launch_bounds__(256, 2) small_mma_kernel(int mode)
{
    extern __shared__ char smem[];
    const uint32_t sb = smem_to_u32(smem);
    const int tid  = threadIdx.x;
    const int wid  = tid >> 5;
    const int lane = tid & 31;
    const int wm   = wid >> 2;          // 0..1 (M 32-halves)
    const int wn   = wid & 3;           // 0..3 (N 16-quarters)
    const int i0   = blockIdx.x * 64;
    const int j0   = blockIdx.y * 64;
    const int b    = blockIdx.z;
    const size_t bo = (size_t)b * DM * DM;
    const __half* __restrict__ Abase =
        ((mode == 0) ? g_Wvh : (g_M1h + bo)) + (size_t)i0 * DM;
    const __half* __restrict__ Bbase =
        ((mode == 0) ? (g_Gh + bo) : g_Wth) + (size_t)j0 * DM;
    __half* __restrict__ C = ((mode == 0) ? g_M1h : g_KVh) + bo;

    const int a_row = wm * 32 + ((lane >> 3) & 1) * 8 + (lane & 7);
    const int a_byt = ((lane >> 4) & 1) * 16;
    const int b_row = wn * 16 + ((lane >> 4) & 1) * 8 + (lane & 7);
    const int b_byt = ((lane >> 3) & 1) * 16;

    float acc[2][2][4];
#pragma unroll
    for (int mt = 0; mt < 2; mt++)
#pragma unroll
        for (int nt = 0; nt < 2; nt++)
#pragma unroll
            for (int q = 0; q < 4; q++) acc[mt][nt][q] = 0.f;

    NT_STAGE64(Abase, Bbase, DM, 0, 0);

    const int NCH = DM / 64;     // 8
    for (int kc = 0; kc < NCH; kc++) {
        const int cur = kc & 1;
        if (kc + 1 < NCH) {
            NT_STAGE64(Abase, Bbase, DM, kc + 1, cur ^ 1);
            CP_WAIT(1);
        } else {
            CP_WAIT(0);
        }
        __syncthreads();

        const uint32_t abase = sb + SM64_A + cur * 8192;
        const uint32_t bbase = sb + SM64_B + cur * 8192;
#pragma unroll
        for (int kk = 0; kk < 4; kk++) {
            uint32_t a[2][4], bb[2][2];
#pragma unroll
            for (int mt = 0; mt < 2; mt++) {
                uint32_t off = (uint32_t)((a_row + mt * 16) * 128 + kk * 32 + a_byt);
                ldmx4(a[mt], abase + SW128(off));
            }
            {
                uint32_t off = (uint32_t)(b_row * 128 + kk * 32 + b_byt);
                uint32_t r[4];
                ldmx4(r, bbase + SW128(off));
                bb[0][0] = r[0]; bb[0][1] = r[1];
                bb[1][0] = r[2]; bb[1][1] = r[3];
            }
#pragma unroll
            for (int mt = 0; mt < 2; mt++)
#pragma unroll
                for (int nt = 0; nt < 2; nt++)
                    mma16816(acc[mt][nt], a[mt], bb[nt]);
        }
        __syncthreads();
    }

    const int g = lane >> 2;
    const int t = lane & 3;
#pragma unroll
    for (int mt = 0; mt < 2; mt++) {
        const int r = i0 + wm * 32 + mt * 16 + g;
#pragma unroll
        for (int nt = 0; nt < 2; nt++) {
            const int c = j0 + wn * 16 + nt * 8 + t * 2;
            __half2 h0 = __floats2half2_rn(acc[mt][nt][0], acc[mt][nt][1]);
            __half2 h1 = __floats2half2_rn(acc[mt][nt][2], acc[mt][nt][3]);
            *(__half2*)(C + (size_t)r * DM + c) = h0;
            *(__half2*)(C + (size_t)(r + 8) * DM + c) = h1;
        }
    }
}

// ============================================================================
// final GEMM, single-pass fp16 HMMA (128x128 tiles):
//   out[m,j] = first[b][j] + scale * sum_k Xh[m,k] KVh[k,j]
// grid (DM/128, MTOT/128), 256 threads.
// ============================================================================
__global__ void __launch_bounds__(256, 2) final_mma_kernel(float* __restrict__ out)
{
    extern __shared__ char smem[];
    const uint32_t sb = smem_to_u32(smem);
    const int tid  = threadIdx.x;
    const int wid  = tid >> 5;
    const int lane = tid & 31;
    const int wm   = wid >> 2;
    const int wn   = wid & 3;
    const int n0   = blockIdx.x * 128;
    const int m0   = blockIdx.y * 128;
    const int b    = m0 / NSEQ;
    const __half* __restrict__ Abase = g_Xh + (size_t)m0 * DM;
    const __half* __restrict__ Bbase = g_KVh + (size_t)b * DM * DM + (size_t)n0 * DM;

    const int a_row = wm * 64 + ((lane >> 3) & 1) * 8 + (lane & 7);
    const int a_byt = ((lane >> 4) & 1) * 16;
    const int b_row = wn * 32 + ((lane >> 4) & 1) * 8 + (lane & 7);
    const int b_byt = ((lane >> 3) & 1) * 16;

    float acc[4][4][4];
#pragma unroll
    for (int mt = 0; mt < 4; mt++)
#pragma unroll
        for (int nt = 0; nt < 4; nt++)
#pragma unroll
            for (int q = 0; q < 4; q++) acc[mt][nt][q] = 0.f;

    NT_STAGE(Abase, Bbase, DM, 0, 0);

    for (int kc = 0; kc < 8; kc++) {
        const int cur = kc & 1;
        if (kc + 1 < 8) {
            NT_STAGE(Abase, Bbase, DM, kc + 1, cur ^ 1);
            CP_WAIT(1);
        } else {
            CP_WAIT(0);
        }
        __syncthreads();

        const uint32_t abase = sb + SM_A + cur * 16384;
        const uint32_t bbase = sb + SM_B + cur * 16384;
#pragma unroll
        for (int kk = 0; kk < 4; kk++) {
            uint32_t a[4][4], bb[4][2];
#pragma unroll
            for (int mt = 0; mt < 4; mt++) {
                uint32_t off = (uint32_t)((a_row + mt * 16) * 128 + kk * 32 + a_byt);
                ldmx4(a[mt], abase + SW128(off));
            }
#pragma unroll
            for (int p = 0; p < 2; p++) {
                uint32_t off = (uint32_t)((b_row + p * 16) * 128 + kk * 32 + b_byt);
                uint32_t r[4];
                ldmx4(r, bbase + SW128(off));
                bb[p * 2][0] = r[0]; bb[p * 2][1] = r[1];
                bb[p * 2 + 1][0] = r[2]; bb[p * 2 + 1][1] = r[3];
            }
#pragma unroll
            for (int mt = 0; mt < 4; mt++)
#pragma unroll
                for (int nt = 0; nt < 4; nt++)
                    mma16816(acc[mt][nt], a[mt], bb[nt]);
        }
        __syncthreads();
    }

    const float scale = 1.0f / (8192.0f * sqrtf(512.0f));
    const int g = lane >> 2;
    const int t = lane & 3;
#pragma unroll
    for (int mt = 0; mt < 4; mt++) {
        const int r = m0 + wm * 64 + mt * 16 + g;
#pragma unroll
        for (int nt = 0; nt < 4; nt++) {
            const int c = n0 + wn * 32 + nt * 8 + t * 2;
            const float f0 = g_first[b * DM + c];
            const float f1 = g_first[b * DM + c + 1];
            *(float2*)(out + (size_t)r * DM + c) =
                make_float2(f0 + scale * acc[mt][nt][0],
                            f1 + scale * acc[mt][nt][1]);
            *(float2*)(out + (size_t)(r + 8) * DM + c) =
                make_float2(f0 + scale * acc[mt][nt][2],
                            f1 + scale * acc[mt][nt][3]);
        }
    }
}

// ============================================================================
extern "C" void kernel_launch(void* const* d_in, const int* in_sizes, int n_in,
                              void* d_out, int out_size)
{
    (void)in_sizes; (void)n_in; (void)out_size;
    const float* X  = (const float*)d_in[0];
    const float* Wv = (const float*)d_in[1];
    const float* Wt = (const float*)d_in[2];
    float* out = (float*)d_out;

    cudaFuncSetAttribute(final_mma_kernel,
                         cudaFuncAttributeMaxDynamicSharedMemorySize, MMA_SMEM);
    cudaFuncSetAttribute(xtx_mma_kernel,
                         cudaFuncAttributeMaxDynamicSharedMemorySize, MMA_SMEM);
    cudaFuncSetAttribute(small_mma_kernel,
                         cudaFuncAttributeMaxDynamicSharedMemorySize, SMALL_SMEM);

    // 0) fp16 conversions: X (+transpose, +column sums) and weights (z==BB)
    convert_x_kernel<<<dim3(NSEQ / 64, DM / 64, BB + 1), 256>>>(X, Wv, Wt);
    // 1) G[b] = X[b]^T X[b]  (fp16 HMMA, 128x128 tiles, split-K=16)
    xtx_mma_kernel<<<dim3(10, BB * SPLITK), 256, MMA_SMEM>>>();
    // 2) reduce + mirror G -> fp16, with meanx stage A in blocks >= 4096
    reduce_g_kernel<<<dim3(4096 + 64), 256>>>();
    // 3) first = mean(X) @ Wv^T
    first_kernel<<<dim3(64), 256>>>(Wv);
    // 4) M1[b] = Wv @ G[b]; KVt[b] = M1[b] @ Wtheta^T  (64x64 tiles)
    small_mma_kernel<<<dim3(8, 8, BB), 256, SMALL_SMEM>>>(0);
    small_mma_kernel<<<dim3(8, 8, BB), 256, SMALL_SMEM>>>(1);
    // 5) out = first + scale * X @ KV   (fp16 HMMA)
    final_mma_kernel<<<dim3(DM / 128, MTOT / 128), 256, MMA_SMEM>>>(out);
}

// round 17
// speedup vs baseline: 1.1625x; 1.0119x over previous
#include <cuda_runtime.h>
#include <cuda_fp16.h>
#include <math.h>
#include <stdint.h>

#define BB     4
#define NSEQ   8192
#define DM     512
#define MTOT   (BB * NSEQ)       // 32768
#define SPLITK 16
#define KC     (NSEQ / SPLITK)   // 512
#define NCHK   (NSEQ / 64)       // 128 mean partial chunks

// ---------------- scratch (static device memory; referenced ONLY from device
// code — host-side use of these symbols silently hits host memory via ATS) ---
__device__ float g_P  [SPLITK * BB * DM * DM];  // X^T X split-K partials
__device__ float g_Pm [BB * NCHK * DM];         // column-sum partials (fused)
__device__ float g_Pm2[BB * 16 * DM];           // meanx stage-A partials
__device__ float g_xm [BB * DM];                // finished mean of X
__device__ float g_first[BB * DM];
__device__ __half g_Xh [(size_t)MTOT * DM];     // fp16 X       [b*n][d]
__device__ __half g_Xt [(size_t)BB * DM * NSEQ];// fp16 X^T     [b][d][n]
__device__ __half g_Gh [BB * DM * DM];          // fp16 G = X^T X (symmetric)
__device__ __half g_M1h[BB * DM * DM];          // fp16 Wv @ G
__device__ __half g_KVh[BB * DM * DM];          // fp16 KV^T    [j][k]
__device__ __half g_Wvh[DM * DM];               // fp16 Wv
__device__ __half g_Wth[DM * DM];               // fp16 Wtheta

__constant__ int c_ti[10] = {0,0,0,0,1,1,1,2,2,3};
__constant__ int c_tj[10] = {0,1,2,3,1,2,3,2,3,3};

#define SW128(x) ((x) ^ (((x) >> 3) & 0x70))

__device__ __forceinline__ uint32_t smem_to_u32(const void* p) {
    uint32_t a;
    asm("{ .reg .u64 t; cvta.to.shared.u64 t, %1; cvt.u32.u64 %0, t; }"
        : "=r"(a) : "l"(p));
    return a;
}
__device__ __forceinline__ void ldmx4(uint32_t r[4], uint32_t addr) {
    asm volatile("ldmatrix.sync.aligned.m8n8.x4.shared.b16 {%0,%1,%2,%3}, [%4];"
        : "=r"(r[0]), "=r"(r[1]), "=r"(r[2]), "=r"(r[3]) : "r"(addr));
}
__device__ __forceinline__ void mma16816(float c[4], const uint32_t a[4],
                                         const uint32_t b[2]) {
    asm volatile("mma.sync.aligned.m16n8k16.row.col.f32.f16.f16.f32 "
        "{%0,%1,%2,%3}, {%4,%5,%6,%7}, {%8,%9}, {%0,%1,%2,%3};"
        : "+f"(c[0]), "+f"(c[1]), "+f"(c[2]), "+f"(c[3])
        : "r"(a[0]), "r"(a[1]), "r"(a[2]), "r"(a[3]), "r"(b[0]), "r"(b[1]));
}
__device__ __forceinline__ void cp_async16(uint32_t dst, const void* src) {
    asm volatile("cp.async.cg.shared.global [%0], [%1], 16;"
        :: "r"(dst), "l"(src) : "memory");
}
#define CP_COMMIT() asm volatile("cp.async.commit_group;" ::: "memory")
#define CP_WAIT(n)  asm volatile("cp.async.wait_group %0;" :: "n"(n) : "memory")

#define SM_A 0                    // 2 bufs x 16384
#define SM_B 32768                // 2 bufs x 16384
#define MMA_SMEM 65536

// generic NT stage (128x128 tiles)
#define NT_STAGE(Abase, Bbase, stride, kc, buf) do { \
        _Pragma("unroll") \
        for (int i = tid; i < 2048; i += 256) { \
            const int arr = i >> 10; \
            const int idx = i & 1023; \
            const int row = idx >> 3; \
            const int cg  = idx & 7; \
            const uint32_t sw = SW128((uint32_t)(row * 128 + cg * 16)); \
            const uint32_t dst = sb + (arr ? SM_B : SM_A) + (buf) * 16384 + sw; \
            const __half* src = (arr ? (Bbase) : (Abase)) \
                + (size_t)row * (stride) + (kc) * 64 + cg * 8; \
            cp_async16(dst, src); \
        } \
        CP_COMMIT(); \
    } while (0)

// 64x64 tile stage
#define SM64_A 0                  // 2 bufs x 8192
#define SM64_B 16384              // 2 bufs x 8192
#define SMALL_SMEM 32768
#define NT_STAGE64(Abase, Bbase, stride, kc, buf) do { \
        _Pragma("unroll") \
        for (int i = tid; i < 1024; i += 256) { \
            const int arr = i >> 9; \
            const int idx = i & 511; \
            const int row = idx >> 3; \
            const int cg  = idx & 7; \
            const uint32_t sw = SW128((uint32_t)(row * 128 + cg * 16)); \
            const uint32_t dst = sb + (arr ? SM64_B : SM64_A) + (buf) * 8192 + sw; \
            const __half* src = (arr ? (Bbase) : (Abase)) \
                + (size_t)row * (stride) + (kc) * 64 + cg * 8; \
            cp_async16(dst, src); \
        } \
        CP_COMMIT(); \
    } while (0)

// ============================================================================
// fp16 conversion of X + fused transpose + fused column-sum partials,
// with Wv/Wtheta conversion folded in as the z==BB slab.
// grid (NSEQ/64, DM/64, BB+1), 256 threads.
// ============================================================================
__global__ void convert_x_kernel(const float* __restrict__ X,
                                 const float* __restrict__ Wv,
                                 const float* __restrict__ Wt)
{
    if (blockIdx.z == BB) {
        if (blockIdx.y >= 2) return;               // 256 weight blocks
        const int blk = blockIdx.y * 128 + blockIdx.x;
        const float* src = (blk < 128) ? Wv : Wt;
        __half* dst = (blk < 128) ? g_Wvh : g_Wth;
        const size_t base = ((size_t)(blk & 127) * 256 + threadIdx.x) * 8;
        float4 v0 = *(const float4*)(src + base);
        float4 v1 = *(const float4*)(src + base + 4);
        uint4 u; __half* ph = (__half*)&u;
        ph[0] = __float2half_rn(v0.x); ph[1] = __float2half_rn(v0.y);
        ph[2] = __float2half_rn(v0.z); ph[3] = __float2half_rn(v0.w);
        ph[4] = __float2half_rn(v1.x); ph[5] = __float2half_rn(v1.y);
        ph[6] = __float2half_rn(v1.z); ph[7] = __float2half_rn(v1.w);
        *(uint4*)(dst + base) = u;
        return;
    }

    __shared__ __half s[64][72];
    __shared__ float  psum[16][64];
    const int b  = blockIdx.z;
    const int n0 = blockIdx.x * 64;
    const int d0 = blockIdx.y * 64;
    const int t  = threadIdx.x;

    float4 cs = make_float4(0.f, 0.f, 0.f, 0.f);
#pragma unroll
    for (int i = t; i < 1024; i += 256) {
        const int row = i >> 4;
        const int cq  = (i & 15) << 2;
        float4 v = *(const float4*)(X + ((size_t)b * NSEQ + n0 + row) * DM + d0 + cq);
        cs.x += v.x; cs.y += v.y; cs.z += v.z; cs.w += v.w;
        __half h0 = __float2half_rn(v.x), h1 = __float2half_rn(v.y);
        __half h2 = __float2half_rn(v.z), h3 = __float2half_rn(v.w);
        uint2 u; __half* ph = (__half*)&u;
        ph[0] = h0; ph[1] = h1; ph[2] = h2; ph[3] = h3;
        *(uint2*)(g_Xh + ((size_t)b * NSEQ + n0 + row) * DM + d0 + cq) = u;
        s[cq + 0][row] = h0; s[cq + 1][row] = h1;
        s[cq + 2][row] = h2; s[cq + 3][row] = h3;
    }
    *(float4*)&psum[t >> 4][(t & 15) << 2] = cs;
    __syncthreads();

#pragma unroll
    for (int i = t; i < 1024; i += 256) {
        const int dr = i >> 4;
        const int nq = (i & 15) << 2;
        uint2 u; __half* ph = (__half*)&u;
        ph[0] = s[dr][nq]; ph[1] = s[dr][nq + 1];
        ph[2] = s[dr][nq + 2]; ph[3] = s[dr][nq + 3];
        *(uint2*)(g_Xt + ((size_t)b * DM + d0 + dr) * NSEQ + n0 + nq) = u;
    }

    if (t < 64) {
        float v = 0.f;
#pragma unroll
        for (int rg = 0; rg < 16; rg++) v += psum[rg][t];
        g_Pm[((size_t)b * NCHK + blockIdx.x) * DM + d0 + t] = v;
    }
}

// ============================================================================
// X^T X on fp16 HMMA (128x128 tiles): grid (10, BB*SPLITK), 256 threads.
// ============================================================================
__global__ void __launch_bounds__(256, 2) xtx_mma_kernel()
{
    extern __shared__ char smem[];
    const uint32_t sb = smem_to_u32(smem);
    const int tid  = threadIdx.x;
    const int wid  = tid >> 5;
    const int lane = tid & 31;
    const int wm   = wid >> 2;
    const int wn   = wid & 3;
    const int ti   = c_ti[blockIdx.x];
    const int tj   = c_tj[blockIdx.x];
    const int b    = blockIdx.y / SPLITK;
    const int s    = blockIdx.y % SPLITK;
    const __half* __restrict__ Abase =
        g_Xt + ((size_t)b * DM + ti * 128) * NSEQ + (size_t)s * KC;
    const __half* __restrict__ Bbase =
        g_Xt + ((size_t)b * DM + tj * 128) * NSEQ + (size_t)s * KC;

    const int a_row = wm * 64 + ((lane >> 3) & 1) * 8 + (lane & 7);
    const int a_byt = ((lane >> 4) & 1) * 16;
    const int b_row = wn * 32 + ((lane >> 4) & 1) * 8 + (lane & 7);
    const int b_byt = ((lane >> 3) & 1) * 16;

    float acc[4][4][4];
#pragma unroll
    for (int mt = 0; mt < 4; mt++)
#pragma unroll
        for (int nt = 0; nt < 4; nt++)
#pragma unroll
            for (int q = 0; q < 4; q++) acc[mt][nt][q] = 0.f;

    NT_STAGE(Abase, Bbase, NSEQ, 0, 0);

    const int NCH = KC / 64;     // 8
    for (int kc = 0; kc < NCH; kc++) {
        const int cur = kc & 1;
        if (kc + 1 < NCH) {
            NT_STAGE(Abase, Bbase, NSEQ, kc + 1, cur ^ 1);
            CP_WAIT(1);
        } else {
            CP_WAIT(0);
        }
        __syncthreads();

        const uint32_t abase = sb + SM_A + cur * 16384;
        const uint32_t bbase = sb + SM_B + cur * 16384;
#pragma unroll
        for (int kk = 0; kk < 4; kk++) {
            uint32_t a[4][4], bb[4][2];
#pragma unroll
            for (int mt = 0; mt < 4; mt++) {
                uint32_t off = (uint32_t)((a_row + mt * 16) * 128 + kk * 32 + a_byt);
                ldmx4(a[mt], abase + SW128(off));
            }
#pragma unroll
            for (int p = 0; p < 2; p++) {
                uint32_t off = (uint32_t)((b_row + p * 16) * 128 + kk * 32 + b_byt);
                uint32_t r[4];
                ldmx4(r, bbase + SW128(off));
                bb[p * 2][0] = r[0]; bb[p * 2][1] = r[1];
                bb[p * 2 + 1][0] = r[2]; bb[p * 2 + 1][1] = r[3];
            }
#pragma unroll
            for (int mt = 0; mt < 4; mt++)
#pragma unroll
                for (int nt = 0; nt < 4; nt++)
                    mma16816(acc[mt][nt], a[mt], bb[nt]);
        }
        __syncthreads();
    }

    float* C = g_P + ((size_t)(s * BB + b)) * DM * DM;
    const int g = lane >> 2;
    const int t = lane & 3;
#pragma unroll
    for (int mt = 0; mt < 4; mt++) {
        const int r = ti * 128 + wm * 64 + mt * 16 + g;
#pragma unroll
        for (int nt = 0; nt < 4; nt++) {
            const int c = tj * 128 + wn * 32 + nt * 8 + t * 2;
            *(float2*)(C + (size_t)r * DM + c) =
                make_float2(acc[mt][nt][0], acc[mt][nt][1]);
            *(float2*)(C + (size_t)(r + 8) * DM + c) =
                make_float2(acc[mt][nt][2], acc[mt][nt][3]);
        }
    }
}

// ============================================================================
// split-K reduce + symmetric mirror (fp16 out), with meanx stage A folded
// into blocks >= 4096. grid (4096 + 64), 256 threads.
// ============================================================================
__global__ void reduce_g_kernel()
{
    const int blk = blockIdx.x;
    if (blk >= 4096) {
        const int m  = blk - 4096;
        const int b  = m >> 4;
        const int sg = m & 15;
        for (int j = threadIdx.x; j < DM; j += 256) {
            const float* p = g_Pm + ((size_t)b * NCHK + sg * 8) * DM + j;
            float s0 = p[0 * DM] + p[4 * DM];
            float s1 = p[1 * DM] + p[5 * DM];
            float s2 = p[2 * DM] + p[6 * DM];
            float s3 = p[3 * DM] + p[7 * DM];
            g_Pm2[((size_t)b * 16 + sg) * DM + j] = (s0 + s1) + (s2 + s3);
        }
        return;
    }
    const int idx = blk * 256 + threadIdx.x;
    const int b = idx >> 18;
    const int r = idx & (DM * DM - 1);
    const int i = r >> 9;
    const int j = r & 511;
    if (j < i) return;
    float s = 0.f;
#pragma unroll
    for (int sp = 0; sp < SPLITK; sp++)
        s += g_P[((size_t)(sp * BB + b)) * DM * DM + r];
    __half h = __float2half_rn(s);
    g_Gh[(size_t)b * DM * DM + (size_t)i * DM + j] = h;
    g_Gh[(size_t)b * DM * DM + (size_t)j * DM + i] = h;
}

// mean finish: xm[b][d] = (sum of 16 stage-A partials) / NSEQ.
// grid (4), 512 threads (one d per thread).
__global__ void meanx3_kernel()
{
    const int b = blockIdx.x;
    const int d = threadIdx.x;
    float s = 0.f;
#pragma unroll
    for (int k = 0; k < 16; k++)
        s += g_Pm2[((size_t)b * 16 + k) * DM + d];
    g_xm[b * DM + d] = s * (1.0f / (float)NSEQ);
}

// first[b][j] = xm[b] . Wv[j] for all batches. grid (64), 256 threads.
__global__ void first_kernel(const float* __restrict__ Wv)
{
    __shared__ float xm[BB][DM];
    const int t = threadIdx.x;
    for (int i = t; i < BB * DM; i += 256)
        xm[i >> 9][i & 511] = g_xm[i];
    __syncthreads();

    const int wid  = t >> 5;
    const int lane = t & 31;
    const int j = blockIdx.x * 8 + wid;
    const float* w = Wv + (size_t)j * DM;
    float a0 = 0.f, a1 = 0.f, a2 = 0.f, a3 = 0.f;
    for (int k = lane; k < DM; k += 32) {
        const float wv = w[k];
        a0 += xm[0][k] * wv;
        a1 += xm[1][k] * wv;
        a2 += xm[2][k] * wv;
        a3 += xm[3][k] * wv;
    }
#pragma unroll
    for (int o = 16; o; o >>= 1) {
        a0 += __shfl_xor_sync(0xFFFFFFFFu, a0, o);
        a1 += __shfl_xor_sync(0xFFFFFFFFu, a1, o);
        a2 += __shfl_xor_sync(0xFFFFFFFFu, a2, o);
        a3 += __shfl_xor_sync(0xFFFFFFFFu, a3, o);
    }
    if (lane == 0) {
        g_first[0 * DM + j] = a0;
        g_first[1 * DM + j] = a1;
        g_first[2 * DM + j] = a2;
        g_first[3 * DM + j] = a3;
    }
}

// ============================================================================
// small batched 512^3 GEMM on fp16 HMMA, 64x64 tiles.
// mode 0: M1[b] = Wvh @ Gh[b]; mode 1: KVt[b] = M1h[b] @ Wth^T.
// grid (8, 8, BB), 256 threads; warps 2(M=32) x 4(N=16).
// ============================================================================
__global__ void __launch_bounds__(256, 2) small_mma_kernel(int mode)
{
    extern __shared__ char smem[];
    const uint32_t sb = smem_to_u32(smem);
    const int tid  = threadIdx.x;
    const int wid  = tid >> 5;
    const int lane = tid & 31;
    const int wm   = wid >> 2;
    const int wn   = wid & 3;
    const int i0   = blockIdx.x * 64;
    const int j0   = blockIdx.y * 64;
    const int b    = blockIdx.z;
    const size_t bo = (size_t)b * DM * DM;
    const __half* __restrict__ Abase =
        ((mode == 0) ? g_Wvh : (g_M1h + bo)) + (size_t)i0 * DM;
    const __half* __restrict__ Bbase =
        ((mode == 0) ? (g_Gh + bo) : g_Wth) + (size_t)j0 * DM;
    __half* __restrict__ C = ((mode == 0) ? g_M1h : g_KVh) + bo;

    const int a_row = wm * 32 + ((lane >> 3) & 1) * 8 + (lane & 7);
    const int a_byt = ((lane >> 4) & 1) * 16;
    const int b_row = wn * 16 + ((lane >> 4) & 1) * 8 + (lane & 7);
    const int b_byt = ((lane >> 3) & 1) * 16;

    float acc[2][2][4];
#pragma unroll
    for (int mt = 0; mt < 2; mt++)
#pragma unroll
        for (int nt = 0; nt < 2; nt++)
#pragma unroll
            for (int q = 0; q < 4; q++) acc[mt][nt][q] = 0.f;

    NT_STAGE64(Abase, Bbase, DM, 0, 0);

    const int NCH = DM / 64;     // 8
    for (int kc = 0; kc < NCH; kc++) {
        const int cur = kc & 1;
        if (kc + 1 < NCH) {
            NT_STAGE64(Abase, Bbase, DM, kc + 1, cur ^ 1);
            CP_WAIT(1);
        } else {
            CP_WAIT(0);
        }
        __syncthreads();

        const uint32_t abase = sb + SM64_A + cur * 8192;
        const uint32_t bbase = sb + SM64_B + cur * 8192;
#pragma unroll
        for (int kk = 0; kk < 4; kk++) {
            uint32_t a[2][4], bb[2][2];
#pragma unroll
            for (int mt = 0; mt < 2; mt++) {
                uint32_t off = (uint32_t)((a_row + mt * 16) * 128 + kk * 32 + a_byt);
                ldmx4(a[mt], abase + SW128(off));
            }
            {
                uint32_t off = (uint32_t)(b_row * 128 + kk * 32 + b_byt);
                uint32_t r[4];
                ldmx4(r, bbase + SW128(off));
                bb[0][0] = r[0]; bb[0][1] = r[1];
                bb[1][0] = r[2]; bb[1][1] = r[3];
            }
#pragma unroll
            for (int mt = 0; mt < 2; mt++)
#pragma unroll
                for (int nt = 0; nt < 2; nt++)
                    mma16816(acc[mt][nt], a[mt], bb[nt]);
        }
        __syncthreads();
    }

    const int g = lane >> 2;
    const int t = lane & 3;
#pragma unroll
    for (int mt = 0; mt < 2; mt++) {
        const int r = i0 + wm * 32 + mt * 16 + g;
#pragma unroll
        for (int nt = 0; nt < 2; nt++) {
            const int c = j0 + wn * 16 + nt * 8 + t * 2;
            __half2 h0 = __floats2half2_rn(acc[mt][nt][0], acc[mt][nt][1]);
            __half2 h1 = __floats2half2_rn(acc[mt][nt][2], acc[mt][nt][3]);
            *(__half2*)(C + (size_t)r * DM + c) = h0;
            *(__half2*)(C + (size_t)(r + 8) * DM + c) = h1;
        }
    }
}

// ============================================================================
// final GEMM, single-pass fp16 HMMA (128x128 tiles):
//   out[m,j] = first[b][j] + scale * sum_k Xh[m,k] KVh[k,j]
// grid (DM/128, MTOT/128), 256 threads.
// ============================================================================
__global__ void __launch_bounds__(256, 2) final_mma_kernel(float* __restrict__ out)
{
    extern __shared__ char smem[];
    const uint32_t sb = smem_to_u32(smem);
    const int tid  = threadIdx.x;
    const int wid  = tid >> 5;
    const int lane = tid & 31;
    const int wm   = wid >> 2;
    const int wn   = wid & 3;
    const int n0   = blockIdx.x * 128;
    const int m0   = blockIdx.y * 128;
    const int b    = m0 / NSEQ;
    const __half* __restrict__ Abase = g_Xh + (size_t)m0 * DM;
    const __half* __restrict__ Bbase = g_KVh + (size_t)b * DM * DM + (size_t)n0 * DM;

    const int a_row = wm * 64 + ((lane >> 3) & 1) * 8 + (lane & 7);
    const int a_byt = ((lane >> 4) & 1) * 16;
    const int b_row = wn * 32 + ((lane >> 4) & 1) * 8 + (lane & 7);
    const int b_byt = ((lane >> 3) & 1) * 16;

    float acc[4][4][4];
#pragma unroll
    for (int mt = 0; mt < 4; mt++)
#pragma unroll
        for (int nt = 0; nt < 4; nt++)
#pragma unroll
            for (int q = 0; q < 4; q++) acc[mt][nt][q] = 0.f;

    NT_STAGE(Abase, Bbase, DM, 0, 0);

    for (int kc = 0; kc < 8; kc++) {
        const int cur = kc & 1;
        if (kc + 1 < 8) {
            NT_STAGE(Abase, Bbase, DM, kc + 1, cur ^ 1);
            CP_WAIT(1);
        } else {
            CP_WAIT(0);
        }
        __syncthreads();

        const uint32_t abase = sb + SM_A + cur * 16384;
        const uint32_t bbase = sb + SM_B + cur * 16384;
#pragma unroll
        for (int kk = 0; kk < 4; kk++) {
            uint32_t a[4][4], bb[4][2];
#pragma unroll
            for (int mt = 0; mt < 4; mt++) {
                uint32_t off = (uint32_t)((a_row + mt * 16) * 128 + kk * 32 + a_byt);
                ldmx4(a[mt], abase + SW128(off));
            }
#pragma unroll
            for (int p = 0; p < 2; p++) {
                uint32_t off = (uint32_t)((b_row + p * 16) * 128 + kk * 32 + b_byt);
                uint32_t r[4];
                ldmx4(r, bbase + SW128(off));
                bb[p * 2][0] = r[0]; bb[p * 2][1] = r[1];
                bb[p * 2 + 1][0] = r[2]; bb[p * 2 + 1][1] = r[3];
            }
#pragma unroll
            for (int mt = 0; mt < 4; mt++)
#pragma unroll
                for (int nt = 0; nt < 4; nt++)
                    mma16816(acc[mt][nt], a[mt], bb[nt]);
        }
        __syncthreads();
    }

    const float scale = 1.0f / (8192.0f * sqrtf(512.0f));
    const int g = lane >> 2;
    const int t = lane & 3;
#pragma unroll
    for (int mt = 0; mt < 4; mt++) {
        const int r = m0 + wm * 64 + mt * 16 + g;
#pragma unroll
        for (int nt = 0; nt < 4; nt++) {
            const int c = n0 + wn * 32 + nt * 8 + t * 2;
            const float f0 = g_first[b * DM + c];
            const float f1 = g_first[b * DM + c + 1];
            *(float2*)(out + (size_t)r * DM + c) =
                make_float2(f0 + scale * acc[mt][nt][0],
                            f1 + scale * acc[mt][nt][1]);
            *(float2*)(out + (size_t)(r + 8) * DM + c) =
                make_float2(f0 + scale * acc[mt][nt][2],
                            f1 + scale * acc[mt][nt][3]);
        }
    }
}

// ============================================================================
extern "C" void kernel_launch(void* const* d_in, const int* in_sizes, int n_in,
                              void* d_out, int out_size)
{
    (void)in_sizes; (void)n_in; (void)out_size;
    const float* X  = (const float*)d_in[0];
    const float* Wv = (const float*)d_in[1];
    const float* Wt = (const float*)d_in[2];
    float* out = (float*)d_out;

    cudaFuncSetAttribute(final_mma_kernel,
                         cudaFuncAttributeMaxDynamicSharedMemorySize, MMA_SMEM);
    cudaFuncSetAttribute(xtx_mma_kernel,
                         cudaFuncAttributeMaxDynamicSharedMemorySize, MMA_SMEM);
    cudaFuncSetAttribute(small_mma_kernel,
                         cudaFuncAttributeMaxDynamicSharedMemorySize, SMALL_SMEM);

    // 0) fp16 conversions: X (+transpose, +column sums) and weights (z==BB)
    convert_x_kernel<<<dim3(NSEQ / 64, DM / 64, BB + 1), 256>>>(X, Wv, Wt);
    // 1) G[b] = X[b]^T X[b]  (fp16 HMMA, 128x128 tiles, split-K=16)
    xtx_mma_kernel<<<dim3(10, BB * SPLITK), 256, MMA_SMEM>>>();
    // 2) reduce + mirror G -> fp16, with meanx stage A in blocks >= 4096
    reduce_g_kernel<<<dim3(4096 + 64), 256>>>();
    // 3) mean finish, then first = mean(X) @ Wv^T
    meanx3_kernel<<<dim3(BB), 512>>>();
    first_kernel<<<dim3(64), 256>>>(Wv);
    // 4) M1[b] = Wv @ G[b]; KVt[b] = M1[b] @ Wtheta^T  (64x64 tiles)
    small_mma_kernel<<<dim3(8, 8, BB), 256, SMALL_SMEM>>>(0);
    small_mma_kernel<<<dim3(8, 8, BB), 256, SMALL_SMEM>>>(1);
    // 5) out = first + scale * X @ KV   (fp16 HMMA)
    final_mma_kernel<<<dim3(DM / 128, MTOT / 128), 256, MMA_SMEM>>>(out);
}